// round 11
// baseline (speedup 1.0000x reference)
#include <cuda_runtime.h>
#include <cuda_fp16.h>
#include <stdint.h>
#include <math.h>

#define NN 100000
#define NE 524288
#define EPSC 1e-5f
#define EDGE_TILES 4096
#define NODE_TILES 391
#define GRID_P 148
#define SQRT1_2 0.70710678118654752440f

// g_T fp16, t-grouped fragment layout. Per 128-half section:
//   half index t*32 + 2*j + b   <->   logical col 8*j + 2*t + b
// Sections per node row (1024B): [x@W1a | x@W1b | x@Wga | x@Wgb]
static __device__ uint4 g_T4[(size_t)NN * 64];    // NN * 1024 bytes

// Pre-swizzled fp16 weight images
static __device__ char g_B1f_[65536];      // [W1e|Wge] 256n x 128k
static __device__ char g_W2f_[32768];      // W2 128n x 128k
static __device__ char g_BNf_[2][65536];   // node W1 / Wg, 256n x 128k

// ---------------- helpers ----------------
__device__ __forceinline__ int swb(int row, int b) {      // 256B rows, xor swizzle
    return row * 256 + (b ^ ((row & 7) << 4));
}
__device__ __forceinline__ int gofs(int row, int col) {   // fp32 gate buf, 256B rows
    return row * 256 + ((col * 4) ^ ((row & 7) << 5));
}
__device__ __forceinline__ uint32_t smem_u32(const void* p) {
    uint32_t a;
    asm("{ .reg .u64 t; cvta.to.shared.u64 t, %1; cvt.u32.u64 %0, t; }" : "=r"(a) : "l"(p));
    return a;
}
__device__ __forceinline__ void ldm_x4(uint32_t f[4], uint32_t addr) {
    asm volatile("ldmatrix.sync.aligned.m8n8.x4.shared.b16 {%0,%1,%2,%3}, [%4];"
                 : "=r"(f[0]), "=r"(f[1]), "=r"(f[2]), "=r"(f[3]) : "r"(addr));
}
__device__ __forceinline__ void mma16816h(float* c, uint32_t a0, uint32_t a1, uint32_t a2,
                                          uint32_t a3, uint32_t b0, uint32_t b1) {
    asm volatile("mma.sync.aligned.m16n8k16.row.col.f32.f16.f16.f32 "
                 "{%0,%1,%2,%3}, {%4,%5,%6,%7}, {%8,%9}, {%0,%1,%2,%3};"
                 : "+f"(c[0]), "+f"(c[1]), "+f"(c[2]), "+f"(c[3])
                 : "r"(a0), "r"(a1), "r"(a2), "r"(a3), "r"(b0), "r"(b1));
}
__device__ __forceinline__ void mma1(float* acc, const uint32_t a[4],
                                     const char* B, int n, int o0) {
    uint32_t b0 = *(const uint32_t*)(B + swb(n, o0));
    uint32_t b1 = *(const uint32_t*)(B + swb(n, o0 + 16));
    mma16816h(acc, a[0], a[1], a[2], a[3], b0, b1);
}
__device__ __forceinline__ void load_afrag(uint32_t f[4], const char* base, int lr, int o0) {
    f[0] = *(const uint32_t*)(base + swb(lr, o0));
    f[1] = *(const uint32_t*)(base + swb(lr + 8, o0));
    f[2] = *(const uint32_t*)(base + swb(lr, o0 + 16));
    f[3] = *(const uint32_t*)(base + swb(lr + 8, o0 + 16));
}
#define PAIR_BAR(id) asm volatile("bar.sync %0, 64;" :: "r"(id) : "memory")
#define ACC2(vv, jj, c0) { float2 _f = __half22float2(*reinterpret_cast<const __half2*>(&(vv))); \
                           acc[jj][c0] += _f.x; acc[jj][(c0) + 1] += _f.y; }

// ============================================================================
// Prep kernel
// ============================================================================
__global__ void prep_kernel(const float* __restrict__ W1,
                            const float* __restrict__ Wg,
                            const float* __restrict__ W2)
{
    int i = blockIdx.x * 256 + threadIdx.x;
    float v;
    char* dst;
    int o;
    if (i < 32768) {
        int n = i >> 7, k = i & 127;
        v = (n < 128) ? W1[(size_t)(256 + k) * 128 + n]
                      : Wg[(size_t)(256 + k) * 128 + (n - 128)];
        o = swb(n, 2 * k); dst = g_B1f_;
    } else if (i < 49152) {
        int j = i - 32768;
        int n = j >> 7, k = j & 127;
        v = W2[(size_t)k * 128 + n];
        o = swb(n, 2 * k); dst = g_W2f_;
    } else {
        int j = i - 49152;
        int q = j >> 15; j &= 32767;
        int n = j >> 7, k = j & 127;
        const float* W = q ? Wg : W1;
        v = (n < 128) ? W[(size_t)k * 128 + n]
                      : W[(size_t)(128 + k) * 128 + (n - 128)];
        o = swb(n, 2 * k); dst = g_BNf_[q];
    }
    *(__half*)(dst + o) = __float2half_rn(v);
}

// ============================================================================
// Node kernel: 512 threads, 256-node tiles, t-grouped fp16 g_T output.
// smem: B 64K | AH 64K = 131072
// ============================================================================
__global__ __launch_bounds__(512, 1)
void node_mma_kernel(const float* __restrict__ x)
{
    extern __shared__ char sm[];
    char* B  = sm;
    char* AH = sm + 65536;

    const int tid = threadIdx.x;
    const int w = tid >> 5, lane = tid & 31;
    const int g = lane >> 2, t = lane & 3;
    const int lr = w * 16 + g;

    for (int q = 0; q < 2; q++) {
        __syncthreads();
        for (int i = tid; i < 4096; i += 512)
            ((float4*)B)[i] = ((const float4*)g_BNf_[q])[i];
        __syncthreads();

        for (int tile = blockIdx.x; tile < NODE_TILES; tile += gridDim.x) {
            #pragma unroll
            for (int i = 0; i < 16; i++) {
                int r = w * 16 + i;
                int node = tile * 256 + r;
                float4 v = (node < NN) ? *(const float4*)(x + (size_t)node * 128 + lane * 4)
                                       : make_float4(0.f, 0.f, 0.f, 0.f);
                __half2 h0 = __floats2half2_rn(v.x, v.y);
                __half2 h1 = __floats2half2_rn(v.z, v.w);
                *(uint2*)(AH + swb(r, 8 * lane)) =
                    make_uint2(*(uint32_t*)&h0, *(uint32_t*)&h1);
            }
            __syncwarp();

            const int n1 = tile * 256 + lr;
            const int n2 = n1 + 8;
            #pragma unroll
            for (int nh = 0; nh < 2; nh++) {
                float acc[16][4];
                #pragma unroll
                for (int j = 0; j < 16; j++)
                    #pragma unroll
                    for (int c = 0; c < 4; c++) acc[j][c] = 0.f;
                #pragma unroll
                for (int s = 0; s < 8; s++) {
                    int o0 = 32 * s + 4 * t;
                    uint32_t a[4];
                    load_afrag(a, AH, lr, o0);
                    #pragma unroll
                    for (int j = 0; j < 16; j++)
                        mma1(acc[j], a, B, nh * 128 + j * 8 + g, o0);
                }
                // t-grouped store: lane's 16 half2 are 64B contiguous
                const size_t secoff = (size_t)(q * 256 + nh * 128) * 2 + (size_t)t * 64;
                #pragma unroll
                for (int e2s = 0; e2s < 2; e2s++) {
                    int n = e2s ? n2 : n1;
                    int c0 = e2s ? 2 : 0;
                    if (n < NN) {
                        char* s1 = (char*)g_T4 + (size_t)n * 1024 + secoff;
                        #pragma unroll
                        for (int q4 = 0; q4 < 4; q4++) {
                            __half2 a0 = __floats2half2_rn(acc[4*q4+0][c0], acc[4*q4+0][c0+1]);
                            __half2 a1 = __floats2half2_rn(acc[4*q4+1][c0], acc[4*q4+1][c0+1]);
                            __half2 a2 = __floats2half2_rn(acc[4*q4+2][c0], acc[4*q4+2][c0+1]);
                            __half2 a3 = __floats2half2_rn(acc[4*q4+3][c0], acc[4*q4+3][c0+1]);
                            *(uint4*)(s1 + 16 * q4) =
                                make_uint4(*(uint32_t*)&a0, *(uint32_t*)&a1,
                                           *(uint32_t*)&a2, *(uint32_t*)&a3);
                        }
                    }
                }
            }
            __syncwarp();
        }
    }
}

// ============================================================================
// Edge kernel: 512 threads = 8 pairs {h-warp w, gate-warp w+8}, 16 edges/pair.
// smem: B1@0 64K | W2@64K 32K | A1@96K 32K | A2@128K 32K | G@160K 32K |
//       S@192K 2K | S2@194K 1K   = 199680 B
// A1/A2 pair-slices are reused as the fp32 r-bounce buffer for coalesced out.
// ============================================================================
__global__ __launch_bounds__(512, 1)
void edge_mma_kernel(const int* __restrict__ ei, const float* __restrict__ ea,
                     const float* __restrict__ b1, const float* __restrict__ g1,
                     const float* __restrict__ be1, const float* __restrict__ b2,
                     const float* __restrict__ bg, const float* __restrict__ gn,
                     const float* __restrict__ bn, float* __restrict__ out,
                     int tile0)
{
    extern __shared__ char sm[];
    char* B1  = sm;
    char* W2s = sm + 65536;
    char* A1  = sm + 98304;
    char* A2  = sm + 131072;
    char* G   = sm + 163840;
    float* S  = (float*)(sm + 196608);
    float* S2 = (float*)(sm + 198656);

    const int tid = threadIdx.x;
    const int w = tid >> 5, lane = tid & 31;
    const int g = lane >> 2, t = lane & 3;
    const int pw = w & 7;
    const bool isH = (w < 8);
    const int lr = pw * 16 + g;
    const int barid = 1 + pw;

    const int mid = lane >> 3, rr = lane & 7;
    const int aRowOff = (mid & 1) * 8 + rr;
    const int aHs = (mid >> 1) * 16;
    const int bNoff = (mid >> 1) * 8 + rr;
    const int bHs = (mid & 1) * 16;
    const uint32_t rx = (uint32_t)(rr << 4);

    const uint32_t B1u = smem_u32(B1);
    const uint32_t W2u = smem_u32(W2s);
    const uint32_t aBase1 = smem_u32(A1) + (uint32_t)(pw * 16 + aRowOff) * 256;
    const uint32_t aBase2 = smem_u32(A2) + (uint32_t)(pw * 16 + aRowOff) * 256;

    const float4 gn4 = *(const float4*)(gn + lane * 4);
    const float4 bn4 = *(const float4*)(bn + lane * 4);

    for (int i = tid; i < 4096; i += 512) ((float4*)B1)[i] = ((const float4*)g_B1f_)[i];
    for (int i = tid; i < 2048; i += 512) ((float4*)W2s)[i] = ((const float4*)g_W2f_)[i];
    __syncthreads();

    const int tile_end = tile0 + EDGE_TILES / 4;
    for (int tile = tile0 + blockIdx.x; tile < tile_end; tile += gridDim.x) {
        PAIR_BAR(barid);   // prev tile's r-bounce reads done before A1 restage

        const int e1 = tile * 128 + lr;
        const int e2 = e1 + 8;
        const int is1 = ei[e1], id1 = ei[NE + e1];
        const int is2 = ei[e2], id2 = ei[NE + e2];

        // ---- stage A1 (fp16 ea) ----
        #pragma unroll
        for (int i = 0; i < 8; i++) {
            int r = pw * 16 + (isH ? i : 8 + i);
            float4 v = *(const float4*)(ea + (size_t)(tile * 128 + r) * 128 + lane * 4);
            __half2 h0 = __floats2half2_rn(v.x, v.y);
            __half2 h1 = __floats2half2_rn(v.z, v.w);
            *(uint2*)(A1 + swb(r, 8 * lane)) =
                make_uint2(*(uint32_t*)&h0, *(uint32_t*)&h1);
        }
        PAIR_BAR(barid);

        // ---- bias init + vectorized gathers (t-grouped g_T) ----
        const int offs = isH ? 0 : 512;      // byte offsets of role sections
        const int offd = isH ? 256 : 768;
        const char* Tb = (const char*)g_T4;
        const char* P1s = Tb + (size_t)is1 * 1024 + offs + t * 64;
        const char* P1d = Tb + (size_t)id1 * 1024 + offd + t * 64;
        const char* P2s = Tb + (size_t)is2 * 1024 + offs + t * 64;
        const char* P2d = Tb + (size_t)id2 * 1024 + offd + t * 64;
        const float* bias = isH ? b1 : bg;

        float acc[16][4];
        #pragma unroll
        for (int j = 0; j < 16; j++) {
            float2 bb = *(const float2*)(bias + j * 8 + 2 * t);
            acc[j][0] = bb.x; acc[j][1] = bb.y;
            acc[j][2] = bb.x; acc[j][3] = bb.y;
        }
        #pragma unroll
        for (int q = 0; q < 4; q++) {
            uint4 u1 = *(const uint4*)(P1s + 16 * q);
            uint4 u2 = *(const uint4*)(P1d + 16 * q);
            uint4 u3 = *(const uint4*)(P2s + 16 * q);
            uint4 u4 = *(const uint4*)(P2d + 16 * q);
            int j0 = 4 * q;
            ACC2(u1.x, j0 + 0, 0) ACC2(u1.y, j0 + 1, 0) ACC2(u1.z, j0 + 2, 0) ACC2(u1.w, j0 + 3, 0)
            ACC2(u2.x, j0 + 0, 0) ACC2(u2.y, j0 + 1, 0) ACC2(u2.z, j0 + 2, 0) ACC2(u2.w, j0 + 3, 0)
            ACC2(u3.x, j0 + 0, 2) ACC2(u3.y, j0 + 1, 2) ACC2(u3.z, j0 + 2, 2) ACC2(u3.w, j0 + 3, 2)
            ACC2(u4.x, j0 + 0, 2) ACC2(u4.y, j0 + 1, 2) ACC2(u4.z, j0 + 2, 2) ACC2(u4.w, j0 + 3, 2)
        }

        // ---- GEMM1 (A from A1 via ldmatrix) ----
        const int nbase = isH ? 0 : 128;
        #pragma unroll
        for (int s = 0; s < 8; s++) {
            uint32_t a[4];
            ldm_x4(a, aBase1 + (((uint32_t)(32 * s + aHs)) ^ rx));
            #pragma unroll
            for (int jp = 0; jp < 8; jp++) {
                uint32_t b[4];
                int n = nbase + jp * 16 + bNoff;
                ldm_x4(b, B1u + (uint32_t)n * 256 + (((uint32_t)(32 * s + bHs)) ^ rx));
                mma16816h(acc[2 * jp],     a[0], a[1], a[2], a[3], b[0], b[1]);
                mma16816h(acc[2 * jp + 1], a[0], a[1], a[2], a[3], b[2], b[3]);
            }
        }

        // ---- per-role nonlinearity ----
        if (isH) {
            float s1 = 0.f, q1 = 0.f, s2 = 0.f, q2 = 0.f;
            #pragma unroll
            for (int j = 0; j < 16; j++) {
                s1 += acc[j][0] + acc[j][1];
                q1 += acc[j][0] * acc[j][0] + acc[j][1] * acc[j][1];
                s2 += acc[j][2] + acc[j][3];
                q2 += acc[j][2] * acc[j][2] + acc[j][3] * acc[j][3];
            }
            #pragma unroll
            for (int o = 1; o <= 2; o <<= 1) {
                s1 += __shfl_xor_sync(0xFFFFFFFFu, s1, o);
                q1 += __shfl_xor_sync(0xFFFFFFFFu, q1, o);
                s2 += __shfl_xor_sync(0xFFFFFFFFu, s2, o);
                q2 += __shfl_xor_sync(0xFFFFFFFFu, q2, o);
            }
            float mu1 = s1 * (1.f / 128.f), rs1 = rsqrtf(q1 * (1.f / 128.f) - mu1 * mu1 + EPSC);
            float mu2 = s2 * (1.f / 128.f), rs2 = rsqrtf(q2 * (1.f / 128.f) - mu2 * mu2 + EPSC);
            #pragma unroll
            for (int j = 0; j < 16; j++) {
                int col = j * 8 + 2 * t;
                float2 gv = *(const float2*)(g1 + col);
                float2 bv = *(const float2*)(be1 + col);
                float y0 = (acc[j][0] - mu1) * rs1 * gv.x + bv.x;
                float y1 = (acc[j][1] - mu1) * rs1 * gv.y + bv.y;
                float y2 = (acc[j][2] - mu2) * rs2 * gv.x + bv.x;
                float y3 = (acc[j][3] - mu2) * rs2 * gv.y + bv.y;
                acc[j][0] = 0.5f * y0 * (1.f + erff(y0 * SQRT1_2));
                acc[j][1] = 0.5f * y1 * (1.f + erff(y1 * SQRT1_2));
                acc[j][2] = 0.5f * y2 * (1.f + erff(y2 * SQRT1_2));
                acc[j][3] = 0.5f * y3 * (1.f + erff(y3 * SQRT1_2));
            }
        } else {
            #pragma unroll
            for (int j = 0; j < 16; j++)
                #pragma unroll
                for (int c = 0; c < 4; c++)
                    acc[j][c] = 1.f / (1.f + expf(-acc[j][c]));
            #pragma unroll
            for (int j = 0; j < 8; j++) {
                int col = j * 8 + 2 * t;
                *(float2*)(G + gofs(lr, col))     = make_float2(acc[j][0], acc[j][1]);
                *(float2*)(G + gofs(lr + 8, col)) = make_float2(acc[j][2], acc[j][3]);
            }
        }
        PAIR_BAR(barid);   // G written

        if (isH) {         // write A2 = gelu(h) fp16 into A2 region
            #pragma unroll
            for (int j = 0; j < 16; j++) {
                __half2 p0 = __floats2half2_rn(acc[j][0], acc[j][1]);
                __half2 p1 = __floats2half2_rn(acc[j][2], acc[j][3]);
                int b = 16 * j + 4 * t;
                *(uint32_t*)(A2 + swb(lr, b))     = *(uint32_t*)&p0;
                *(uint32_t*)(A2 + swb(lr + 8, b)) = *(uint32_t*)&p1;
            }
        }
        PAIR_BAR(barid);   // A2 visible

        // ---- GEMM2 split: h -> n 0..63, gate -> n 64..127 ----
        const int nb2 = isH ? 0 : 64;
        float acc2[8][4];
        #pragma unroll
        for (int jl = 0; jl < 8; jl++)
            #pragma unroll
            for (int c = 0; c < 4; c++) acc2[jl][c] = 0.f;
        #pragma unroll
        for (int s = 0; s < 8; s++) {
            uint32_t a[4];
            ldm_x4(a, aBase2 + (((uint32_t)(32 * s + aHs)) ^ rx));
            #pragma unroll
            for (int jp = 0; jp < 4; jp++) {
                uint32_t b[4];
                int n = nb2 + jp * 16 + bNoff;
                ldm_x4(b, W2u + (uint32_t)n * 256 + (((uint32_t)(32 * s + bHs)) ^ rx));
                mma16816h(acc2[2 * jp],     a[0], a[1], a[2], a[3], b[0], b[1]);
                mma16816h(acc2[2 * jp + 1], a[0], a[1], a[2], a[3], b[2], b[3]);
            }
        }

        // ---- r = (h2+b2)*gate + ea(fp16 from A1 smem) ----
        float r[8][4];
        #pragma unroll
        for (int jl = 0; jl < 8; jl++) {
            int col = nb2 + jl * 8 + 2 * t;
            float2 bv = *(const float2*)(b2 + col);
            uint32_t ha = *(const uint32_t*)(A1 + swb(lr, 2 * col));
            uint32_t hb = *(const uint32_t*)(A1 + swb(lr + 8, 2 * col));
            float2 eA = __half22float2(*reinterpret_cast<const __half2*>(&ha));
            float2 eB = __half22float2(*reinterpret_cast<const __half2*>(&hb));
            float g0, g1v, g2, g3;
            if (isH) {
                float2 gA = *(const float2*)(G + gofs(lr, col));
                float2 gB = *(const float2*)(G + gofs(lr + 8, col));
                g0 = gA.x; g1v = gA.y; g2 = gB.x; g3 = gB.y;
            } else {
                g0 = acc[8 + jl][0]; g1v = acc[8 + jl][1];
                g2 = acc[8 + jl][2]; g3 = acc[8 + jl][3];
            }
            r[jl][0] = (acc2[jl][0] + bv.x) * g0 + eA.x;
            r[jl][1] = (acc2[jl][1] + bv.y) * g1v + eA.y;
            r[jl][2] = (acc2[jl][2] + bv.x) * g2 + eB.x;
            r[jl][3] = (acc2[jl][3] + bv.y) * g3 + eB.y;
        }

        // ---- final LN stats: partial sums + pair exchange ----
        float s1 = 0.f, q1 = 0.f, s2 = 0.f, q2 = 0.f;
        #pragma unroll
        for (int jl = 0; jl < 8; jl++) {
            s1 += r[jl][0] + r[jl][1];
            q1 += r[jl][0] * r[jl][0] + r[jl][1] * r[jl][1];
            s2 += r[jl][2] + r[jl][3];
            q2 += r[jl][2] * r[jl][2] + r[jl][3] * r[jl][3];
        }
        #pragma unroll
        for (int o = 1; o <= 2; o <<= 1) {
            s1 += __shfl_xor_sync(0xFFFFFFFFu, s1, o);
            q1 += __shfl_xor_sync(0xFFFFFFFFu, q1, o);
            s2 += __shfl_xor_sync(0xFFFFFFFFu, s2, o);
            q2 += __shfl_xor_sync(0xFFFFFFFFu, q2, o);
        }
        {
            float* sp = S + pw * 64 + (isH ? 0 : 32) + g * 4;
            if (t == 0) { sp[0] = s1; sp[1] = q1; sp[2] = s2; sp[3] = q2; }
        }
        PAIR_BAR(barid);   // also: all A1(ea)/G reads complete -> slices reusable
        {
            const float* sp = S + pw * 64 + (isH ? 32 : 0) + g * 4;
            s1 += sp[0]; q1 += sp[1]; s2 += sp[2]; q2 += sp[3];
        }
        float mu1 = s1 * (1.f / 128.f), rs1 = rsqrtf(q1 * (1.f / 128.f) - mu1 * mu1 + EPSC);
        float mu2 = s2 * (1.f / 128.f), rs2 = rsqrtf(q2 * (1.f / 128.f) - mu2 * mu2 + EPSC);

        if (isH && t == 0) {
            S2[2 * lr] = mu1;         S2[2 * lr + 1] = rs1;
            S2[2 * (lr + 8)] = mu2;   S2[2 * (lr + 8) + 1] = rs2;
        }
        // raw r fragments -> bounce buffer (A1 slice = rows 0..7, A2 slice = 8..15)
        {
            char* rbA = A1 + pw * 4096 + g * 512;   // row lr   (local g)
            char* rbB = A2 + pw * 4096 + g * 512;   // row lr+8 (local 8+g)
            const int xr = g << 4;
            #pragma unroll
            for (int jl = 0; jl < 8; jl++) {
                int col = nb2 + jl * 8 + 2 * t;
                *(float2*)(rbA + ((col * 4) ^ xr)) = make_float2(r[jl][0], r[jl][1]);
                *(float2*)(rbB + ((col * 4) ^ xr)) = make_float2(r[jl][2], r[jl][3]);
            }
        }
        PAIR_BAR(barid);   // r + stats visible

        // ---- coalesced LN+store: h-warp rows 0..7, gate rows 8..15 ----
        {
            const char* rbase = (isH ? A1 : A2) + pw * 4096;
            #pragma unroll
            for (int i = 0; i < 8; i++) {
                int row = pw * 16 + (isH ? i : 8 + i);
                float4 v = *(const float4*)(rbase + i * 512 + ((lane * 16) ^ (i << 4)));
                float mu = S2[2 * row], rs = S2[2 * row + 1];
                float4 o;
                o.x = (v.x - mu) * rs * gn4.x + bn4.x;
                o.y = (v.y - mu) * rs * gn4.y + bn4.y;
                o.z = (v.z - mu) * rs * gn4.z + bn4.z;
                o.w = (v.w - mu) * rs * gn4.w + bn4.w;
                *(float4*)(out + (size_t)(tile * 128 + row) * 128 + lane * 4) = o;
            }
        }
    }
}

// ---------------------------------------------------------------------------
extern "C" void kernel_launch(void* const* d_in, const int* in_sizes, int n_in,
                              void* d_out, int out_size)
{
    const float* x   = (const float*)d_in[0];
    const int*   ei  = (const int*)d_in[1];
    const float* ea  = (const float*)d_in[2];
    const float* W1  = (const float*)d_in[3];
    const float* b1  = (const float*)d_in[4];
    const float* g1  = (const float*)d_in[5];
    const float* be1 = (const float*)d_in[6];
    const float* W2  = (const float*)d_in[7];
    const float* b2  = (const float*)d_in[8];
    const float* Wg  = (const float*)d_in[9];
    const float* bg  = (const float*)d_in[10];
    const float* gn  = (const float*)d_in[11];
    const float* bn  = (const float*)d_in[12];
    float*       out = (float*)d_out;

    const int node_smem = 131072;
    const int edge_smem = 199680;
    cudaFuncSetAttribute(node_mma_kernel, cudaFuncAttributeMaxDynamicSharedMemorySize, node_smem);
    cudaFuncSetAttribute(edge_mma_kernel, cudaFuncAttributeMaxDynamicSharedMemorySize, edge_smem);

    prep_kernel<<<448, 256>>>(W1, Wg, W2);
    node_mma_kernel<<<GRID_P, 512, node_smem>>>(x);
    for (int part = 0; part < 4; part++)
        edge_mma_kernel<<<GRID_P, 512, edge_smem>>>(ei, ea, b1, g1, be1, b2, bg, gn, bn,
                                                    out, part * (EDGE_TILES / 4));
}

// round 12
// speedup vs baseline: 1.3873x; 1.3873x over previous
#include <cuda_runtime.h>
#include <cuda_fp16.h>
#include <stdint.h>
#include <math.h>

#define NN 100000
#define NE 524288
#define EPSC 1e-5f
#define EDGE_TILES 4096
#define NODE_TILES 391
#define GRID_P 148
#define SQRT1_2 0.70710678118654752440f

// g_T fp16, t-grouped fragment layout. Per 128-col section (256B):
//   half index t*32 + 2*j + b  <->  logical col 8*j + 2*t + b
// Sections per node row (1024B): [x@W1a | x@W1b | x@Wga | x@Wgb]
static __device__ uint4 g_T4[(size_t)NN * 64];    // NN * 1024 bytes

// Pre-swizzled fp16 weight images
static __device__ char g_B1f_[65536];      // [W1e|Wge] 256n x 128k
static __device__ char g_W2f_[32768];      // W2 128n x 128k
static __device__ char g_BNf_[2][65536];   // node W1 / Wg, 256n x 128k

// ---------------- helpers ----------------
__device__ __forceinline__ int swb(int row, int b) {      // 256B rows, xor swizzle
    return row * 256 + (b ^ ((row & 7) << 4));
}
__device__ __forceinline__ int gofs(int row, int col) {   // fp32 gate buf, 256B rows
    return row * 256 + ((col * 4) ^ ((row & 7) << 5));
}
__device__ __forceinline__ uint32_t smem_u32(const void* p) {
    uint32_t a;
    asm("{ .reg .u64 t; cvta.to.shared.u64 t, %1; cvt.u32.u64 %0, t; }" : "=r"(a) : "l"(p));
    return a;
}
__device__ __forceinline__ void ldm_x4(uint32_t f[4], uint32_t addr) {
    asm volatile("ldmatrix.sync.aligned.m8n8.x4.shared.b16 {%0,%1,%2,%3}, [%4];"
                 : "=r"(f[0]), "=r"(f[1]), "=r"(f[2]), "=r"(f[3]) : "r"(addr));
}
__device__ __forceinline__ void mma16816h(float* c, uint32_t a0, uint32_t a1, uint32_t a2,
                                          uint32_t a3, uint32_t b0, uint32_t b1) {
    asm volatile("mma.sync.aligned.m16n8k16.row.col.f32.f16.f16.f32 "
                 "{%0,%1,%2,%3}, {%4,%5,%6,%7}, {%8,%9}, {%0,%1,%2,%3};"
                 : "+f"(c[0]), "+f"(c[1]), "+f"(c[2]), "+f"(c[3])
                 : "r"(a0), "r"(a1), "r"(a2), "r"(a3), "r"(b0), "r"(b1));
}
__device__ __forceinline__ void mma1(float* acc, const uint32_t a[4],
                                     const char* B, int n, int o0) {
    uint32_t b0 = *(const uint32_t*)(B + swb(n, o0));
    uint32_t b1 = *(const uint32_t*)(B + swb(n, o0 + 16));
    mma16816h(acc, a[0], a[1], a[2], a[3], b0, b1);
}
__device__ __forceinline__ void load_afrag(uint32_t f[4], const char* base, int lr, int o0) {
    f[0] = *(const uint32_t*)(base + swb(lr, o0));
    f[1] = *(const uint32_t*)(base + swb(lr + 8, o0));
    f[2] = *(const uint32_t*)(base + swb(lr, o0 + 16));
    f[3] = *(const uint32_t*)(base + swb(lr + 8, o0 + 16));
}
#define PAIR_BAR(id) asm volatile("bar.sync %0, 64;" :: "r"(id) : "memory")
#define ACC2(vv, jj, c0) { float2 _f = __half22float2(*reinterpret_cast<const __half2*>(&(vv))); \
                           acc[jj][c0] += _f.x; acc[jj][(c0) + 1] += _f.y; }

// ============================================================================
// Prep kernel
// ============================================================================
__global__ void prep_kernel(const float* __restrict__ W1,
                            const float* __restrict__ Wg,
                            const float* __restrict__ W2)
{
    int i = blockIdx.x * 256 + threadIdx.x;
    float v;
    char* dst;
    int o;
    if (i < 32768) {
        int n = i >> 7, k = i & 127;
        v = (n < 128) ? W1[(size_t)(256 + k) * 128 + n]
                      : Wg[(size_t)(256 + k) * 128 + (n - 128)];
        o = swb(n, 2 * k); dst = g_B1f_;
    } else if (i < 49152) {
        int j = i - 32768;
        int n = j >> 7, k = j & 127;
        v = W2[(size_t)k * 128 + n];
        o = swb(n, 2 * k); dst = g_W2f_;
    } else {
        int j = i - 49152;
        int q = j >> 15; j &= 32767;
        int n = j >> 7, k = j & 127;
        const float* W = q ? Wg : W1;
        v = (n < 128) ? W[(size_t)k * 128 + n]
                      : W[(size_t)(128 + k) * 128 + (n - 128)];
        o = swb(n, 2 * k); dst = g_BNf_[q];
    }
    *(__half*)(dst + o) = __float2half_rn(v);
}

// ============================================================================
// Node kernel: 512 threads, 256-node tiles, t-grouped fp16 g_T output.
// smem: B 64K | AH 64K = 131072
// ============================================================================
__global__ __launch_bounds__(512, 1)
void node_mma_kernel(const float* __restrict__ x)
{
    extern __shared__ char sm[];
    char* B  = sm;
    char* AH = sm + 65536;

    const int tid = threadIdx.x;
    const int w = tid >> 5, lane = tid & 31;
    const int g = lane >> 2, t = lane & 3;
    const int lr = w * 16 + g;

    for (int q = 0; q < 2; q++) {
        __syncthreads();
        for (int i = tid; i < 4096; i += 512)
            ((float4*)B)[i] = ((const float4*)g_BNf_[q])[i];
        __syncthreads();

        for (int tile = blockIdx.x; tile < NODE_TILES; tile += gridDim.x) {
            #pragma unroll
            for (int i = 0; i < 16; i++) {
                int r = w * 16 + i;
                int node = tile * 256 + r;
                float4 v = (node < NN) ? *(const float4*)(x + (size_t)node * 128 + lane * 4)
                                       : make_float4(0.f, 0.f, 0.f, 0.f);
                __half2 h0 = __floats2half2_rn(v.x, v.y);
                __half2 h1 = __floats2half2_rn(v.z, v.w);
                *(uint2*)(AH + swb(r, 8 * lane)) =
                    make_uint2(*(uint32_t*)&h0, *(uint32_t*)&h1);
            }
            __syncwarp();

            const int n1 = tile * 256 + lr;
            const int n2 = n1 + 8;
            #pragma unroll
            for (int nh = 0; nh < 2; nh++) {
                float acc[16][4];
                #pragma unroll
                for (int j = 0; j < 16; j++)
                    #pragma unroll
                    for (int c = 0; c < 4; c++) acc[j][c] = 0.f;
                #pragma unroll
                for (int s = 0; s < 8; s++) {
                    int o0 = 32 * s + 4 * t;
                    uint32_t a[4];
                    load_afrag(a, AH, lr, o0);
                    #pragma unroll
                    for (int j = 0; j < 16; j++)
                        mma1(acc[j], a, B, nh * 128 + j * 8 + g, o0);
                }
                // t-grouped store: lane's 16 half2 are 64B contiguous
                const size_t secoff = (size_t)(q * 256 + nh * 128) * 2 + (size_t)t * 64;
                #pragma unroll
                for (int e2s = 0; e2s < 2; e2s++) {
                    int n = e2s ? n2 : n1;
                    int c0 = e2s ? 2 : 0;
                    if (n < NN) {
                        char* s1 = (char*)g_T4 + (size_t)n * 1024 + secoff;
                        #pragma unroll
                        for (int q4 = 0; q4 < 4; q4++) {
                            __half2 a0 = __floats2half2_rn(acc[4*q4+0][c0], acc[4*q4+0][c0+1]);
                            __half2 a1 = __floats2half2_rn(acc[4*q4+1][c0], acc[4*q4+1][c0+1]);
                            __half2 a2 = __floats2half2_rn(acc[4*q4+2][c0], acc[4*q4+2][c0+1]);
                            __half2 a3 = __floats2half2_rn(acc[4*q4+3][c0], acc[4*q4+3][c0+1]);
                            *(uint4*)(s1 + 16 * q4) =
                                make_uint4(*(uint32_t*)&a0, *(uint32_t*)&a1,
                                           *(uint32_t*)&a2, *(uint32_t*)&a3);
                        }
                    }
                }
            }
            __syncwarp();
        }
    }
}

// ============================================================================
// Edge kernel (R10 structure + t-grouped gathers): 512 threads = 8 pairs.
// smem: B1 64K | W2 32K | AH 32K | G 32K | S 2K = 165888
// ============================================================================
__global__ __launch_bounds__(512, 1)
void edge_mma_kernel(const int* __restrict__ ei, const float* __restrict__ ea,
                     const float* __restrict__ b1, const float* __restrict__ g1,
                     const float* __restrict__ be1, const float* __restrict__ b2,
                     const float* __restrict__ bg, const float* __restrict__ gn,
                     const float* __restrict__ bn, float* __restrict__ out,
                     int tile0)
{
    extern __shared__ char sm[];
    char* B1  = sm;
    char* W2s = sm + 65536;
    char* AH  = sm + 98304;
    char* G   = sm + 131072;
    float* S  = (float*)(sm + 163840);

    const int tid = threadIdx.x;
    const int w = tid >> 5, lane = tid & 31;
    const int g = lane >> 2, t = lane & 3;
    const int pw = w & 7;
    const bool isH = (w < 8);
    const int lr = pw * 16 + g;
    const int barid = 1 + pw;

    const int mid = lane >> 3, rr = lane & 7;
    const int aRowOff = (mid & 1) * 8 + rr;
    const int aHs = (mid >> 1) * 16;
    const int bNoff = (mid >> 1) * 8 + rr;
    const int bHs = (mid & 1) * 16;
    const uint32_t rx = (uint32_t)(rr << 4);

    const uint32_t B1u = smem_u32(B1);
    const uint32_t W2u = smem_u32(W2s);
    const uint32_t aBase = smem_u32(AH) + (uint32_t)(pw * 16 + aRowOff) * 256;

    for (int i = tid; i < 4096; i += 512) ((float4*)B1)[i] = ((const float4*)g_B1f_)[i];
    for (int i = tid; i < 2048; i += 512) ((float4*)W2s)[i] = ((const float4*)g_W2f_)[i];
    __syncthreads();

    const int tile_end = tile0 + EDGE_TILES / 4;
    for (int tile = tile0 + blockIdx.x; tile < tile_end; tile += gridDim.x) {
        // ---- indices early ----
        const int e1 = tile * 128 + lr;
        const int e2 = e1 + 8;
        const int is1 = ei[e1], id1 = ei[NE + e1];
        const int is2 = ei[e2], id2 = ei[NE + e2];

        // ---- stage A1 (fp16 ea) ----
        #pragma unroll
        for (int i = 0; i < 8; i++) {
            int r = pw * 16 + (isH ? i : 8 + i);
            float4 v = *(const float4*)(ea + (size_t)(tile * 128 + r) * 128 + lane * 4);
            __half2 h0 = __floats2half2_rn(v.x, v.y);
            __half2 h1 = __floats2half2_rn(v.z, v.w);
            *(uint2*)(AH + swb(r, 8 * lane)) =
                make_uint2(*(uint32_t*)&h0, *(uint32_t*)&h1);
        }
        PAIR_BAR(barid);

        // ---- bias init + vectorized t-grouped gathers ----
        const int offs = isH ? 0 : 512;      // byte offsets of role sections
        const int offd = isH ? 256 : 768;
        const char* Tb = (const char*)g_T4;
        const char* P1s = Tb + (size_t)is1 * 1024 + offs + t * 64;
        const char* P1d = Tb + (size_t)id1 * 1024 + offd + t * 64;
        const char* P2s = Tb + (size_t)is2 * 1024 + offs + t * 64;
        const char* P2d = Tb + (size_t)id2 * 1024 + offd + t * 64;
        const float* bias = isH ? b1 : bg;

        float acc[16][4];
        #pragma unroll
        for (int j = 0; j < 16; j++) {
            float2 bb = *(const float2*)(bias + j * 8 + 2 * t);
            acc[j][0] = bb.x; acc[j][1] = bb.y;
            acc[j][2] = bb.x; acc[j][3] = bb.y;
        }
        #pragma unroll
        for (int q = 0; q < 4; q++) {
            uint4 u1 = *(const uint4*)(P1s + 16 * q);
            uint4 u2 = *(const uint4*)(P1d + 16 * q);
            uint4 u3 = *(const uint4*)(P2s + 16 * q);
            uint4 u4 = *(const uint4*)(P2d + 16 * q);
            int j0 = 4 * q;
            ACC2(u1.x, j0 + 0, 0) ACC2(u1.y, j0 + 1, 0) ACC2(u1.z, j0 + 2, 0) ACC2(u1.w, j0 + 3, 0)
            ACC2(u2.x, j0 + 0, 0) ACC2(u2.y, j0 + 1, 0) ACC2(u2.z, j0 + 2, 0) ACC2(u2.w, j0 + 3, 0)
            ACC2(u3.x, j0 + 0, 2) ACC2(u3.y, j0 + 1, 2) ACC2(u3.z, j0 + 2, 2) ACC2(u3.w, j0 + 3, 2)
            ACC2(u4.x, j0 + 0, 2) ACC2(u4.y, j0 + 1, 2) ACC2(u4.z, j0 + 2, 2) ACC2(u4.w, j0 + 3, 2)
        }

        // ---- GEMM1 via ldmatrix ----
        const int nbase = isH ? 0 : 128;
        #pragma unroll
        for (int s = 0; s < 8; s++) {
            uint32_t a[4];
            ldm_x4(a, aBase + (((uint32_t)(32 * s + aHs)) ^ rx));
            #pragma unroll
            for (int jp = 0; jp < 8; jp++) {
                uint32_t b[4];
                int n = nbase + jp * 16 + bNoff;
                ldm_x4(b, B1u + (uint32_t)n * 256 + (((uint32_t)(32 * s + bHs)) ^ rx));
                mma16816h(acc[2 * jp],     a[0], a[1], a[2], a[3], b[0], b[1]);
                mma16816h(acc[2 * jp + 1], a[0], a[1], a[2], a[3], b[2], b[3]);
            }
        }

        // ---- per-role nonlinearity ----
        if (isH) {
            float s1 = 0.f, q1 = 0.f, s2 = 0.f, q2 = 0.f;
            #pragma unroll
            for (int j = 0; j < 16; j++) {
                s1 += acc[j][0] + acc[j][1];
                q1 += acc[j][0] * acc[j][0] + acc[j][1] * acc[j][1];
                s2 += acc[j][2] + acc[j][3];
                q2 += acc[j][2] * acc[j][2] + acc[j][3] * acc[j][3];
            }
            #pragma unroll
            for (int o = 1; o <= 2; o <<= 1) {
                s1 += __shfl_xor_sync(0xFFFFFFFFu, s1, o);
                q1 += __shfl_xor_sync(0xFFFFFFFFu, q1, o);
                s2 += __shfl_xor_sync(0xFFFFFFFFu, s2, o);
                q2 += __shfl_xor_sync(0xFFFFFFFFu, q2, o);
            }
            float mu1 = s1 * (1.f / 128.f), rs1 = rsqrtf(q1 * (1.f / 128.f) - mu1 * mu1 + EPSC);
            float mu2 = s2 * (1.f / 128.f), rs2 = rsqrtf(q2 * (1.f / 128.f) - mu2 * mu2 + EPSC);
            #pragma unroll
            for (int j = 0; j < 16; j++) {
                int col = j * 8 + 2 * t;
                float2 gv = *(const float2*)(g1 + col);
                float2 bv = *(const float2*)(be1 + col);
                float y0 = (acc[j][0] - mu1) * rs1 * gv.x + bv.x;
                float y1 = (acc[j][1] - mu1) * rs1 * gv.y + bv.y;
                float y2 = (acc[j][2] - mu2) * rs2 * gv.x + bv.x;
                float y3 = (acc[j][3] - mu2) * rs2 * gv.y + bv.y;
                acc[j][0] = 0.5f * y0 * (1.f + erff(y0 * SQRT1_2));
                acc[j][1] = 0.5f * y1 * (1.f + erff(y1 * SQRT1_2));
                acc[j][2] = 0.5f * y2 * (1.f + erff(y2 * SQRT1_2));
                acc[j][3] = 0.5f * y3 * (1.f + erff(y3 * SQRT1_2));
            }
        } else {
            #pragma unroll
            for (int j = 0; j < 16; j++)
                #pragma unroll
                for (int c = 0; c < 4; c++)
                    acc[j][c] = 1.f / (1.f + expf(-acc[j][c]));
            #pragma unroll
            for (int j = 0; j < 8; j++) {        // sigmoid cols 0..63 -> G
                int col = j * 8 + 2 * t;
                *(float2*)(G + gofs(lr, col))     = make_float2(acc[j][0], acc[j][1]);
                *(float2*)(G + gofs(lr + 8, col)) = make_float2(acc[j][2], acc[j][3]);
            }
        }
        PAIR_BAR(barid);   // A1 reads done; G written

        if (isH) {         // write A2 = gelu(h) fp16
            #pragma unroll
            for (int j = 0; j < 16; j++) {
                __half2 p0 = __floats2half2_rn(acc[j][0], acc[j][1]);
                __half2 p1 = __floats2half2_rn(acc[j][2], acc[j][3]);
                int b = 16 * j + 4 * t;
                *(uint32_t*)(AH + swb(lr, b))     = *(uint32_t*)&p0;
                *(uint32_t*)(AH + swb(lr + 8, b)) = *(uint32_t*)&p1;
            }
        }
        PAIR_BAR(barid);   // A2 visible

        // ---- GEMM2 split: h -> n 0..63, gate -> n 64..127 ----
        const int nb2 = isH ? 0 : 64;
        float acc2[8][4];
        #pragma unroll
        for (int jl = 0; jl < 8; jl++)
            #pragma unroll
            for (int c = 0; c < 4; c++) acc2[jl][c] = 0.f;
        #pragma unroll
        for (int s = 0; s < 8; s++) {
            uint32_t a[4];
            ldm_x4(a, aBase + (((uint32_t)(32 * s + aHs)) ^ rx));
            #pragma unroll
            for (int jp = 0; jp < 4; jp++) {
                uint32_t b[4];
                int n = nb2 + jp * 16 + bNoff;
                ldm_x4(b, W2u + (uint32_t)n * 256 + (((uint32_t)(32 * s + bHs)) ^ rx));
                mma16816h(acc2[2 * jp],     a[0], a[1], a[2], a[3], b[0], b[1]);
                mma16816h(acc2[2 * jp + 1], a[0], a[1], a[2], a[3], b[2], b[3]);
            }
        }

        // ---- epilogue half per warp: r = (h2+b2)*gate + ea ----
        float r[8][4];
        #pragma unroll
        for (int jl = 0; jl < 8; jl++) {
            int col = nb2 + jl * 8 + 2 * t;
            float2 bv = *(const float2*)(b2 + col);
            float2 eA = *(const float2*)(ea + (size_t)e1 * 128 + col);
            float2 eB = *(const float2*)(ea + (size_t)e2 * 128 + col);
            float g0, g1v, g2, g3;
            if (isH) {
                float2 gA = *(const float2*)(G + gofs(lr, col));
                float2 gB = *(const float2*)(G + gofs(lr + 8, col));
                g0 = gA.x; g1v = gA.y; g2 = gB.x; g3 = gB.y;
            } else {
                g0 = acc[8 + jl][0]; g1v = acc[8 + jl][1];
                g2 = acc[8 + jl][2]; g3 = acc[8 + jl][3];
            }
            r[jl][0] = (acc2[jl][0] + bv.x) * g0 + eA.x;
            r[jl][1] = (acc2[jl][1] + bv.y) * g1v + eA.y;
            r[jl][2] = (acc2[jl][2] + bv.x) * g2 + eB.x;
            r[jl][3] = (acc2[jl][3] + bv.y) * g3 + eB.y;
        }

        // ---- final LN: partial sums + pair exchange ----
        float s1 = 0.f, q1 = 0.f, s2 = 0.f, q2 = 0.f;
        #pragma unroll
        for (int jl = 0; jl < 8; jl++) {
            s1 += r[jl][0] + r[jl][1];
            q1 += r[jl][0] * r[jl][0] + r[jl][1] * r[jl][1];
            s2 += r[jl][2] + r[jl][3];
            q2 += r[jl][2] * r[jl][2] + r[jl][3] * r[jl][3];
        }
        #pragma unroll
        for (int o = 1; o <= 2; o <<= 1) {
            s1 += __shfl_xor_sync(0xFFFFFFFFu, s1, o);
            q1 += __shfl_xor_sync(0xFFFFFFFFu, q1, o);
            s2 += __shfl_xor_sync(0xFFFFFFFFu, s2, o);
            q2 += __shfl_xor_sync(0xFFFFFFFFu, q2, o);
        }
        {
            float* sp = S + pw * 64 + (isH ? 0 : 32) + g * 4;
            if (t == 0) { sp[0] = s1; sp[1] = q1; sp[2] = s2; sp[3] = q2; }
        }
        PAIR_BAR(barid);
        {
            const float* sp = S + pw * 64 + (isH ? 32 : 0) + g * 4;
            s1 += sp[0]; q1 += sp[1]; s2 += sp[2]; q2 += sp[3];
        }
        float mu1 = s1 * (1.f / 128.f), rs1 = rsqrtf(q1 * (1.f / 128.f) - mu1 * mu1 + EPSC);
        float mu2 = s2 * (1.f / 128.f), rs2 = rsqrtf(q2 * (1.f / 128.f) - mu2 * mu2 + EPSC);
        #pragma unroll
        for (int jl = 0; jl < 8; jl++) {
            int col = nb2 + jl * 8 + 2 * t;
            float2 gv = *(const float2*)(gn + col);
            float2 bv = *(const float2*)(bn + col);
            float2 o1, o2;
            o1.x = (r[jl][0] - mu1) * rs1 * gv.x + bv.x;
            o1.y = (r[jl][1] - mu1) * rs1 * gv.y + bv.y;
            o2.x = (r[jl][2] - mu2) * rs2 * gv.x + bv.x;
            o2.y = (r[jl][3] - mu2) * rs2 * gv.y + bv.y;
            *(float2*)(out + (size_t)e1 * 128 + col) = o1;
            *(float2*)(out + (size_t)e2 * 128 + col) = o2;
        }
    }
}

// ---------------------------------------------------------------------------
extern "C" void kernel_launch(void* const* d_in, const int* in_sizes, int n_in,
                              void* d_out, int out_size)
{
    const float* x   = (const float*)d_in[0];
    const int*   ei  = (const int*)d_in[1];
    const float* ea  = (const float*)d_in[2];
    const float* W1  = (const float*)d_in[3];
    const float* b1  = (const float*)d_in[4];
    const float* g1  = (const float*)d_in[5];
    const float* be1 = (const float*)d_in[6];
    const float* W2  = (const float*)d_in[7];
    const float* b2  = (const float*)d_in[8];
    const float* Wg  = (const float*)d_in[9];
    const float* bg  = (const float*)d_in[10];
    const float* gn  = (const float*)d_in[11];
    const float* bn  = (const float*)d_in[12];
    float*       out = (float*)d_out;

    const int node_smem = 131072;
    const int edge_smem = 165888;
    cudaFuncSetAttribute(node_mma_kernel, cudaFuncAttributeMaxDynamicSharedMemorySize, node_smem);
    cudaFuncSetAttribute(edge_mma_kernel, cudaFuncAttributeMaxDynamicSharedMemorySize, edge_smem);

    prep_kernel<<<448, 256>>>(W1, Wg, W2);
    node_mma_kernel<<<GRID_P, 512, node_smem>>>(x);
    for (int part = 0; part < 4; part++)
        edge_mma_kernel<<<GRID_P, 512, edge_smem>>>(ei, ea, b1, g1, be1, b2, bg, gn, bn,
                                                    out, part * (EDGE_TILES / 4));
}

// round 13
// speedup vs baseline: 1.5078x; 1.0868x over previous
#include <cuda_runtime.h>
#include <cuda_fp16.h>
#include <stdint.h>
#include <math.h>

#define NN 100000
#define NE 524288
#define EPSC 1e-5f
#define EDGE_TILES 4096
#define NODE_TILES 391
#define GRID_P 148
#define SQRT1_2 0.70710678118654752440f

// g_T fp16, t-grouped fragment layout (q/t swapped for 64B-contiguous gathers).
// Per 128-col section (256B): byte offset q*64 + t*16 holds j=4q..4q+3 half2s:
//   half index q*32 + t*8 + 2*jj + b  <->  logical col 8*(4q+jj) + 2*t + b
// Sections per node row (1024B): [x@W1a | x@W1b | x@Wga | x@Wgb]
static __device__ uint4 g_T4[(size_t)NN * 64];    // NN * 1024 bytes

// Pre-swizzled fp16 weight images
static __device__ char g_B1f_[65536];      // [W1e|Wge] 256n x 128k
static __device__ char g_W2f_[32768];      // W2 128n x 128k
static __device__ char g_BNf_[2][65536];   // node W1 / Wg, 256n x 128k

// ---------------- helpers ----------------
__device__ __forceinline__ int swb(int row, int b) {      // 256B rows, xor swizzle
    return row * 256 + (b ^ ((row & 7) << 4));
}
__device__ __forceinline__ int gofs(int row, int col) {   // fp32 gate buf, 256B rows
    return row * 256 + ((col * 4) ^ ((row & 7) << 5));
}
__device__ __forceinline__ uint32_t smem_u32(const void* p) {
    uint32_t a;
    asm("{ .reg .u64 t; cvta.to.shared.u64 t, %1; cvt.u32.u64 %0, t; }" : "=r"(a) : "l"(p));
    return a;
}
__device__ __forceinline__ void ldm_x4(uint32_t f[4], uint32_t addr) {
    asm volatile("ldmatrix.sync.aligned.m8n8.x4.shared.b16 {%0,%1,%2,%3}, [%4];"
                 : "=r"(f[0]), "=r"(f[1]), "=r"(f[2]), "=r"(f[3]) : "r"(addr));
}
__device__ __forceinline__ void mma16816h(float* c, uint32_t a0, uint32_t a1, uint32_t a2,
                                          uint32_t a3, uint32_t b0, uint32_t b1) {
    asm volatile("mma.sync.aligned.m16n8k16.row.col.f32.f16.f16.f32 "
                 "{%0,%1,%2,%3}, {%4,%5,%6,%7}, {%8,%9}, {%0,%1,%2,%3};"
                 : "+f"(c[0]), "+f"(c[1]), "+f"(c[2]), "+f"(c[3])
                 : "r"(a0), "r"(a1), "r"(a2), "r"(a3), "r"(b0), "r"(b1));
}
__device__ __forceinline__ void mma1(float* acc, const uint32_t a[4],
                                     const char* B, int n, int o0) {
    uint32_t b0 = *(const uint32_t*)(B + swb(n, o0));
    uint32_t b1 = *(const uint32_t*)(B + swb(n, o0 + 16));
    mma16816h(acc, a[0], a[1], a[2], a[3], b0, b1);
}
__device__ __forceinline__ void load_afrag(uint32_t f[4], const char* base, int lr, int o0) {
    f[0] = *(const uint32_t*)(base + swb(lr, o0));
    f[1] = *(const uint32_t*)(base + swb(lr + 8, o0));
    f[2] = *(const uint32_t*)(base + swb(lr, o0 + 16));
    f[3] = *(const uint32_t*)(base + swb(lr + 8, o0 + 16));
}
#define PAIR_BAR(id) asm volatile("bar.sync %0, 64;" :: "r"(id) : "memory")
#define ACC2(vv, jj, c0) { float2 _f = __half22float2(*reinterpret_cast<const __half2*>(&(vv))); \
                           acc[jj][c0] += _f.x; acc[jj][(c0) + 1] += _f.y; }

// ============================================================================
// Prep kernel
// ============================================================================
__global__ void prep_kernel(const float* __restrict__ W1,
                            const float* __restrict__ Wg,
                            const float* __restrict__ W2)
{
    int i = blockIdx.x * 256 + threadIdx.x;
    float v;
    char* dst;
    int o;
    if (i < 32768) {
        int n = i >> 7, k = i & 127;
        v = (n < 128) ? W1[(size_t)(256 + k) * 128 + n]
                      : Wg[(size_t)(256 + k) * 128 + (n - 128)];
        o = swb(n, 2 * k); dst = g_B1f_;
    } else if (i < 49152) {
        int j = i - 32768;
        int n = j >> 7, k = j & 127;
        v = W2[(size_t)k * 128 + n];
        o = swb(n, 2 * k); dst = g_W2f_;
    } else {
        int j = i - 49152;
        int q = j >> 15; j &= 32767;
        int n = j >> 7, k = j & 127;
        const float* W = q ? Wg : W1;
        v = (n < 128) ? W[(size_t)k * 128 + n]
                      : W[(size_t)(128 + k) * 128 + (n - 128)];
        o = swb(n, 2 * k); dst = g_BNf_[q];
    }
    *(__half*)(dst + o) = __float2half_rn(v);
}

// ============================================================================
// Node kernel: 512 threads, 256-node tiles, t-grouped (q/t-swapped) g_T out.
// smem: B 64K | AH 64K = 131072
// ============================================================================
__global__ __launch_bounds__(512, 1)
void node_mma_kernel(const float* __restrict__ x)
{
    extern __shared__ char sm[];
    char* B  = sm;
    char* AH = sm + 65536;

    const int tid = threadIdx.x;
    const int w = tid >> 5, lane = tid & 31;
    const int g = lane >> 2, t = lane & 3;
    const int lr = w * 16 + g;

    for (int q = 0; q < 2; q++) {
        __syncthreads();
        for (int i = tid; i < 4096; i += 512)
            ((float4*)B)[i] = ((const float4*)g_BNf_[q])[i];
        __syncthreads();

        for (int tile = blockIdx.x; tile < NODE_TILES; tile += gridDim.x) {
            #pragma unroll
            for (int i = 0; i < 16; i++) {
                int r = w * 16 + i;
                int node = tile * 256 + r;
                float4 v = (node < NN) ? *(const float4*)(x + (size_t)node * 128 + lane * 4)
                                       : make_float4(0.f, 0.f, 0.f, 0.f);
                __half2 h0 = __floats2half2_rn(v.x, v.y);
                __half2 h1 = __floats2half2_rn(v.z, v.w);
                *(uint2*)(AH + swb(r, 8 * lane)) =
                    make_uint2(*(uint32_t*)&h0, *(uint32_t*)&h1);
            }
            __syncwarp();

            const int n1 = tile * 256 + lr;
            const int n2 = n1 + 8;
            #pragma unroll
            for (int nh = 0; nh < 2; nh++) {
                float acc[16][4];
                #pragma unroll
                for (int j = 0; j < 16; j++)
                    #pragma unroll
                    for (int c = 0; c < 4; c++) acc[j][c] = 0.f;
                #pragma unroll
                for (int s = 0; s < 8; s++) {
                    int o0 = 32 * s + 4 * t;
                    uint32_t a[4];
                    load_afrag(a, AH, lr, o0);
                    #pragma unroll
                    for (int j = 0; j < 16; j++)
                        mma1(acc[j], a, B, nh * 128 + j * 8 + g, o0);
                }
                // q/t-swapped t-grouped store: chunk q4 at q4*64 + t*16
                const size_t secoff = (size_t)(q * 256 + nh * 128) * 2 + (size_t)t * 16;
                #pragma unroll
                for (int e2s = 0; e2s < 2; e2s++) {
                    int n = e2s ? n2 : n1;
                    int c0 = e2s ? 2 : 0;
                    if (n < NN) {
                        char* s1 = (char*)g_T4 + (size_t)n * 1024 + secoff;
                        #pragma unroll
                        for (int q4 = 0; q4 < 4; q4++) {
                            __half2 a0 = __floats2half2_rn(acc[4*q4+0][c0], acc[4*q4+0][c0+1]);
                            __half2 a1 = __floats2half2_rn(acc[4*q4+1][c0], acc[4*q4+1][c0+1]);
                            __half2 a2 = __floats2half2_rn(acc[4*q4+2][c0], acc[4*q4+2][c0+1]);
                            __half2 a3 = __floats2half2_rn(acc[4*q4+3][c0], acc[4*q4+3][c0+1]);
                            *(uint4*)(s1 + 64 * q4) =
                                make_uint4(*(uint32_t*)&a0, *(uint32_t*)&a1,
                                           *(uint32_t*)&a2, *(uint32_t*)&a3);
                        }
                    }
                }
            }
            __syncwarp();
        }
    }
}

// ============================================================================
// Edge kernel: R12 structure + 64B-contiguous gathers + preloaded ea residual.
// smem: B1 64K | W2 32K | AH 32K | G 32K | S 2K = 165888
// ============================================================================
__global__ __launch_bounds__(512, 1)
void edge_mma_kernel(const int* __restrict__ ei, const float* __restrict__ ea,
                     const float* __restrict__ b1, const float* __restrict__ g1,
                     const float* __restrict__ be1, const float* __restrict__ b2,
                     const float* __restrict__ bg, const float* __restrict__ gn,
                     const float* __restrict__ bn, float* __restrict__ out,
                     int tile0)
{
    extern __shared__ char sm[];
    char* B1  = sm;
    char* W2s = sm + 65536;
    char* AH  = sm + 98304;
    char* G   = sm + 131072;
    float* S  = (float*)(sm + 163840);

    const int tid = threadIdx.x;
    const int w = tid >> 5, lane = tid & 31;
    const int g = lane >> 2, t = lane & 3;
    const int pw = w & 7;
    const bool isH = (w < 8);
    const int lr = pw * 16 + g;
    const int barid = 1 + pw;

    const int mid = lane >> 3, rr = lane & 7;
    const int aRowOff = (mid & 1) * 8 + rr;
    const int aHs = (mid >> 1) * 16;
    const int bNoff = (mid >> 1) * 8 + rr;
    const int bHs = (mid & 1) * 16;
    const uint32_t rx = (uint32_t)(rr << 4);

    const uint32_t B1u = smem_u32(B1);
    const uint32_t W2u = smem_u32(W2s);
    const uint32_t aBase = smem_u32(AH) + (uint32_t)(pw * 16 + aRowOff) * 256;

    for (int i = tid; i < 4096; i += 512) ((float4*)B1)[i] = ((const float4*)g_B1f_)[i];
    for (int i = tid; i < 2048; i += 512) ((float4*)W2s)[i] = ((const float4*)g_W2f_)[i];
    __syncthreads();

    const int tile_end = tile0 + EDGE_TILES / 4;
    for (int tile = tile0 + blockIdx.x; tile < tile_end; tile += gridDim.x) {
        // ---- indices early ----
        const int e1 = tile * 128 + lr;
        const int e2 = e1 + 8;
        const int is1 = ei[e1], id1 = ei[NE + e1];
        const int is2 = ei[e2], id2 = ei[NE + e2];

        // ---- stage A1 (fp16 ea) ----
        #pragma unroll
        for (int i = 0; i < 8; i++) {
            int r = pw * 16 + (isH ? i : 8 + i);
            float4 v = *(const float4*)(ea + (size_t)(tile * 128 + r) * 128 + lane * 4);
            __half2 h0 = __floats2half2_rn(v.x, v.y);
            __half2 h1 = __floats2half2_rn(v.z, v.w);
            *(uint2*)(AH + swb(r, 8 * lane)) =
                make_uint2(*(uint32_t*)&h0, *(uint32_t*)&h1);
        }
        PAIR_BAR(barid);

        // ---- bias init + 64B-contiguous t-grouped gathers ----
        const int offs = isH ? 0 : 512;      // byte offsets of role sections
        const int offd = isH ? 256 : 768;
        const char* Tb = (const char*)g_T4;
        const char* P1s = Tb + (size_t)is1 * 1024 + offs + t * 16;
        const char* P1d = Tb + (size_t)id1 * 1024 + offd + t * 16;
        const char* P2s = Tb + (size_t)is2 * 1024 + offs + t * 16;
        const char* P2d = Tb + (size_t)id2 * 1024 + offd + t * 16;
        const float* bias = isH ? b1 : bg;

        float acc[16][4];
        #pragma unroll
        for (int j = 0; j < 16; j++) {
            float2 bb = *(const float2*)(bias + j * 8 + 2 * t);
            acc[j][0] = bb.x; acc[j][1] = bb.y;
            acc[j][2] = bb.x; acc[j][3] = bb.y;
        }
        #pragma unroll
        for (int q = 0; q < 4; q++) {
            uint4 u1 = *(const uint4*)(P1s + 64 * q);
            uint4 u2 = *(const uint4*)(P1d + 64 * q);
            uint4 u3 = *(const uint4*)(P2s + 64 * q);
            uint4 u4 = *(const uint4*)(P2d + 64 * q);
            int j0 = 4 * q;
            ACC2(u1.x, j0 + 0, 0) ACC2(u1.y, j0 + 1, 0) ACC2(u1.z, j0 + 2, 0) ACC2(u1.w, j0 + 3, 0)
            ACC2(u2.x, j0 + 0, 0) ACC2(u2.y, j0 + 1, 0) ACC2(u2.z, j0 + 2, 0) ACC2(u2.w, j0 + 3, 0)
            ACC2(u3.x, j0 + 0, 2) ACC2(u3.y, j0 + 1, 2) ACC2(u3.z, j0 + 2, 2) ACC2(u3.w, j0 + 3, 2)
            ACC2(u4.x, j0 + 0, 2) ACC2(u4.y, j0 + 1, 2) ACC2(u4.z, j0 + 2, 2) ACC2(u4.w, j0 + 3, 2)
        }

        // ---- GEMM1 via ldmatrix ----
        const int nbase = isH ? 0 : 128;
        #pragma unroll
        for (int s = 0; s < 8; s++) {
            uint32_t a[4];
            ldm_x4(a, aBase + (((uint32_t)(32 * s + aHs)) ^ rx));
            #pragma unroll
            for (int jp = 0; jp < 8; jp++) {
                uint32_t b[4];
                int n = nbase + jp * 16 + bNoff;
                ldm_x4(b, B1u + (uint32_t)n * 256 + (((uint32_t)(32 * s + bHs)) ^ rx));
                mma16816h(acc[2 * jp],     a[0], a[1], a[2], a[3], b[0], b[1]);
                mma16816h(acc[2 * jp + 1], a[0], a[1], a[2], a[3], b[2], b[3]);
            }
        }

        // ---- per-role nonlinearity ----
        if (isH) {
            float s1 = 0.f, q1 = 0.f, s2 = 0.f, q2 = 0.f;
            #pragma unroll
            for (int j = 0; j < 16; j++) {
                s1 += acc[j][0] + acc[j][1];
                q1 += acc[j][0] * acc[j][0] + acc[j][1] * acc[j][1];
                s2 += acc[j][2] + acc[j][3];
                q2 += acc[j][2] * acc[j][2] + acc[j][3] * acc[j][3];
            }
            #pragma unroll
            for (int o = 1; o <= 2; o <<= 1) {
                s1 += __shfl_xor_sync(0xFFFFFFFFu, s1, o);
                q1 += __shfl_xor_sync(0xFFFFFFFFu, q1, o);
                s2 += __shfl_xor_sync(0xFFFFFFFFu, s2, o);
                q2 += __shfl_xor_sync(0xFFFFFFFFu, q2, o);
            }
            float mu1 = s1 * (1.f / 128.f), rs1 = rsqrtf(q1 * (1.f / 128.f) - mu1 * mu1 + EPSC);
            float mu2 = s2 * (1.f / 128.f), rs2 = rsqrtf(q2 * (1.f / 128.f) - mu2 * mu2 + EPSC);
            #pragma unroll
            for (int j = 0; j < 16; j++) {
                int col = j * 8 + 2 * t;
                float2 gv = *(const float2*)(g1 + col);
                float2 bv = *(const float2*)(be1 + col);
                float y0 = (acc[j][0] - mu1) * rs1 * gv.x + bv.x;
                float y1 = (acc[j][1] - mu1) * rs1 * gv.y + bv.y;
                float y2 = (acc[j][2] - mu2) * rs2 * gv.x + bv.x;
                float y3 = (acc[j][3] - mu2) * rs2 * gv.y + bv.y;
                acc[j][0] = 0.5f * y0 * (1.f + erff(y0 * SQRT1_2));
                acc[j][1] = 0.5f * y1 * (1.f + erff(y1 * SQRT1_2));
                acc[j][2] = 0.5f * y2 * (1.f + erff(y2 * SQRT1_2));
                acc[j][3] = 0.5f * y3 * (1.f + erff(y3 * SQRT1_2));
            }
        } else {
            #pragma unroll
            for (int j = 0; j < 16; j++)
                #pragma unroll
                for (int c = 0; c < 4; c++)
                    acc[j][c] = 1.f / (1.f + expf(-acc[j][c]));
            #pragma unroll
            for (int j = 0; j < 8; j++) {        // sigmoid cols 0..63 -> G
                int col = j * 8 + 2 * t;
                *(float2*)(G + gofs(lr, col))     = make_float2(acc[j][0], acc[j][1]);
                *(float2*)(G + gofs(lr + 8, col)) = make_float2(acc[j][2], acc[j][3]);
            }
        }
        PAIR_BAR(barid);   // A1 reads done; G written

        if (isH) {         // write A2 = gelu(h) fp16
            #pragma unroll
            for (int j = 0; j < 16; j++) {
                __half2 p0 = __floats2half2_rn(acc[j][0], acc[j][1]);
                __half2 p1 = __floats2half2_rn(acc[j][2], acc[j][3]);
                int b = 16 * j + 4 * t;
                *(uint32_t*)(AH + swb(lr, b))     = *(uint32_t*)&p0;
                *(uint32_t*)(AH + swb(lr + 8, b)) = *(uint32_t*)&p1;
            }
        }
        PAIR_BAR(barid);   // A2 visible

        // ---- preload ea residual (consumed after GEMM2) ----
        const int nb2 = isH ? 0 : 64;
        float2 eAv[8], eBv[8];
        #pragma unroll
        for (int jl = 0; jl < 8; jl++) {
            int col = nb2 + jl * 8 + 2 * t;
            eAv[jl] = *(const float2*)(ea + (size_t)e1 * 128 + col);
            eBv[jl] = *(const float2*)(ea + (size_t)e2 * 128 + col);
        }

        // ---- GEMM2 split: h -> n 0..63, gate -> n 64..127 ----
        float acc2[8][4];
        #pragma unroll
        for (int jl = 0; jl < 8; jl++)
            #pragma unroll
            for (int c = 0; c < 4; c++) acc2[jl][c] = 0.f;
        #pragma unroll
        for (int s = 0; s < 8; s++) {
            uint32_t a[4];
            ldm_x4(a, aBase + (((uint32_t)(32 * s + aHs)) ^ rx));
            #pragma unroll
            for (int jp = 0; jp < 4; jp++) {
                uint32_t b[4];
                int n = nb2 + jp * 16 + bNoff;
                ldm_x4(b, W2u + (uint32_t)n * 256 + (((uint32_t)(32 * s + bHs)) ^ rx));
                mma16816h(acc2[2 * jp],     a[0], a[1], a[2], a[3], b[0], b[1]);
                mma16816h(acc2[2 * jp + 1], a[0], a[1], a[2], a[3], b[2], b[3]);
            }
        }

        // ---- epilogue half per warp: r = (h2+b2)*gate + ea ----
        float r[8][4];
        #pragma unroll
        for (int jl = 0; jl < 8; jl++) {
            int col = nb2 + jl * 8 + 2 * t;
            float2 bv = *(const float2*)(b2 + col);
            float g0, g1v, g2, g3;
            if (isH) {
                float2 gA = *(const float2*)(G + gofs(lr, col));
                float2 gB = *(const float2*)(G + gofs(lr + 8, col));
                g0 = gA.x; g1v = gA.y; g2 = gB.x; g3 = gB.y;
            } else {
                g0 = acc[8 + jl][0]; g1v = acc[8 + jl][1];
                g2 = acc[8 + jl][2]; g3 = acc[8 + jl][3];
            }
            r[jl][0] = (acc2[jl][0] + bv.x) * g0 + eAv[jl].x;
            r[jl][1] = (acc2[jl][1] + bv.y) * g1v + eAv[jl].y;
            r[jl][2] = (acc2[jl][2] + bv.x) * g2 + eBv[jl].x;
            r[jl][3] = (acc2[jl][3] + bv.y) * g3 + eBv[jl].y;
        }

        // ---- final LN: partial sums + pair exchange ----
        float s1 = 0.f, q1 = 0.f, s2 = 0.f, q2 = 0.f;
        #pragma unroll
        for (int jl = 0; jl < 8; jl++) {
            s1 += r[jl][0] + r[jl][1];
            q1 += r[jl][0] * r[jl][0] + r[jl][1] * r[jl][1];
            s2 += r[jl][2] + r[jl][3];
            q2 += r[jl][2] * r[jl][2] + r[jl][3] * r[jl][3];
        }
        #pragma unroll
        for (int o = 1; o <= 2; o <<= 1) {
            s1 += __shfl_xor_sync(0xFFFFFFFFu, s1, o);
            q1 += __shfl_xor_sync(0xFFFFFFFFu, q1, o);
            s2 += __shfl_xor_sync(0xFFFFFFFFu, s2, o);
            q2 += __shfl_xor_sync(0xFFFFFFFFu, q2, o);
        }
        {
            float* sp = S + pw * 64 + (isH ? 0 : 32) + g * 4;
            if (t == 0) { sp[0] = s1; sp[1] = q1; sp[2] = s2; sp[3] = q2; }
        }
        PAIR_BAR(barid);
        {
            const float* sp = S + pw * 64 + (isH ? 32 : 0) + g * 4;
            s1 += sp[0]; q1 += sp[1]; s2 += sp[2]; q2 += sp[3];
        }
        float mu1 = s1 * (1.f / 128.f), rs1 = rsqrtf(q1 * (1.f / 128.f) - mu1 * mu1 + EPSC);
        float mu2 = s2 * (1.f / 128.f), rs2 = rsqrtf(q2 * (1.f / 128.f) - mu2 * mu2 + EPSC);
        #pragma unroll
        for (int jl = 0; jl < 8; jl++) {
            int col = nb2 + jl * 8 + 2 * t;
            float2 gv = *(const float2*)(gn + col);
            float2 bv = *(const float2*)(bn + col);
            float2 o1, o2;
            o1.x = (r[jl][0] - mu1) * rs1 * gv.x + bv.x;
            o1.y = (r[jl][1] - mu1) * rs1 * gv.y + bv.y;
            o2.x = (r[jl][2] - mu2) * rs2 * gv.x + bv.x;
            o2.y = (r[jl][3] - mu2) * rs2 * gv.y + bv.y;
            *(float2*)(out + (size_t)e1 * 128 + col) = o1;
            *(float2*)(out + (size_t)e2 * 128 + col) = o2;
        }
    }
}

// ---------------------------------------------------------------------------
extern "C" void kernel_launch(void* const* d_in, const int* in_sizes, int n_in,
                              void* d_out, int out_size)
{
    const float* x   = (const float*)d_in[0];
    const int*   ei  = (const int*)d_in[1];
    const float* ea  = (const float*)d_in[2];
    const float* W1  = (const float*)d_in[3];
    const float* b1  = (const float*)d_in[4];
    const float* g1  = (const float*)d_in[5];
    const float* be1 = (const float*)d_in[6];
    const float* W2  = (const float*)d_in[7];
    const float* b2  = (const float*)d_in[8];
    const float* Wg  = (const float*)d_in[9];
    const float* bg  = (const float*)d_in[10];
    const float* gn  = (const float*)d_in[11];
    const float* bn  = (const float*)d_in[12];
    float*       out = (float*)d_out;

    const int node_smem = 131072;
    const int edge_smem = 165888;
    cudaFuncSetAttribute(node_mma_kernel, cudaFuncAttributeMaxDynamicSharedMemorySize, node_smem);
    cudaFuncSetAttribute(edge_mma_kernel, cudaFuncAttributeMaxDynamicSharedMemorySize, edge_smem);

    prep_kernel<<<448, 256>>>(W1, Wg, W2);
    node_mma_kernel<<<GRID_P, 512, node_smem>>>(x);
    for (int part = 0; part < 4; part++)
        edge_mma_kernel<<<GRID_P, 512, edge_smem>>>(ei, ea, b1, g1, be1, b2, bg, gn, bn,
                                                    out, part * (EDGE_TILES / 4));
}

// round 14
// speedup vs baseline: 1.5722x; 1.0427x over previous
#include <cuda_runtime.h>
#include <cuda_fp16.h>
#include <stdint.h>
#include <math.h>

#define NN 100000
#define NE 524288
#define EPSC 1e-5f
#define EDGE_TILES 4096
#define NODE_TILES 391
#define GRID_P 148
#define SQRT1_2 0.70710678118654752440f

// g_T fp16, t-grouped fragment layout (q/t swapped for 64B-contiguous gathers).
// Per 128-col section (256B): byte offset q*64 + t*16 holds j=4q..4q+3 half2s:
//   half index q*32 + t*8 + 2*jj + b  <->  logical col 8*(4q+jj) + 2*t + b
// Sections per node row (1024B): [x@W1a | x@W1b | x@Wga | x@Wgb]
static __device__ uint4 g_T4[(size_t)NN * 64];    // NN * 1024 bytes

// Pre-swizzled fp16 weight images
static __device__ char g_B1f_[65536];      // [W1e|Wge] 256n x 128k
static __device__ char g_W2f_[32768];      // W2 128n x 128k
static __device__ char g_BNf_[2][65536];   // node W1 / Wg, 256n x 128k

// ---------------- helpers ----------------
__device__ __forceinline__ int swb(int row, int b) {      // 256B rows, xor swizzle
    return row * 256 + (b ^ ((row & 7) << 4));
}
__device__ __forceinline__ int gofs(int row, int col) {   // fp32 gate buf, 256B rows
    return row * 256 + ((col * 4) ^ ((row & 7) << 5));
}
__device__ __forceinline__ uint32_t smem_u32(const void* p) {
    uint32_t a;
    asm("{ .reg .u64 t; cvta.to.shared.u64 t, %1; cvt.u32.u64 %0, t; }" : "=r"(a) : "l"(p));
    return a;
}
__device__ __forceinline__ void ldm_x4(uint32_t f[4], uint32_t addr) {
    asm volatile("ldmatrix.sync.aligned.m8n8.x4.shared.b16 {%0,%1,%2,%3}, [%4];"
                 : "=r"(f[0]), "=r"(f[1]), "=r"(f[2]), "=r"(f[3]) : "r"(addr));
}
__device__ __forceinline__ void mma16816h(float* c, uint32_t a0, uint32_t a1, uint32_t a2,
                                          uint32_t a3, uint32_t b0, uint32_t b1) {
    asm volatile("mma.sync.aligned.m16n8k16.row.col.f32.f16.f16.f32 "
                 "{%0,%1,%2,%3}, {%4,%5,%6,%7}, {%8,%9}, {%0,%1,%2,%3};"
                 : "+f"(c[0]), "+f"(c[1]), "+f"(c[2]), "+f"(c[3])
                 : "r"(a0), "r"(a1), "r"(a2), "r"(a3), "r"(b0), "r"(b1));
}
// fast sigmoid: MUFU.EX2 + MUFU.RCP path (~1e-6 rel err)
__device__ __forceinline__ float fast_sigmoid(float x) {
    return __fdividef(1.f, 1.f + __expf(-x));
}
// fast erf: Abramowitz-Stegun 7.1.26, max abs err ~1.5e-7, branchless
__device__ __forceinline__ float fast_erf(float z) {
    float az = fabsf(z);
    float t  = __fdividef(1.f, fmaf(0.3275911f, az, 1.f));
    float p  = fmaf(1.061405429f, t, -1.453152027f);
    p = fmaf(p, t, 1.421413741f);
    p = fmaf(p, t, -0.284496736f);
    p = fmaf(p, t, 0.254829592f);
    p *= t;
    float r = 1.f - p * __expf(-az * az);
    return copysignf(r, z);
}
__device__ __forceinline__ float fast_gelu(float y) {
    return 0.5f * y * (1.f + fast_erf(y * SQRT1_2));
}
#define PAIR_BAR(id) asm volatile("bar.sync %0, 64;" :: "r"(id) : "memory")
#define ACC2(vv, jj, c0) { float2 _f = __half22float2(*reinterpret_cast<const __half2*>(&(vv))); \
                           acc[jj][c0] += _f.x; acc[jj][(c0) + 1] += _f.y; }

// ============================================================================
// Prep kernel
// ============================================================================
__global__ void prep_kernel(const float* __restrict__ W1,
                            const float* __restrict__ Wg,
                            const float* __restrict__ W2)
{
    int i = blockIdx.x * 256 + threadIdx.x;
    float v;
    char* dst;
    int o;
    if (i < 32768) {
        int n = i >> 7, k = i & 127;
        v = (n < 128) ? W1[(size_t)(256 + k) * 128 + n]
                      : Wg[(size_t)(256 + k) * 128 + (n - 128)];
        o = swb(n, 2 * k); dst = g_B1f_;
    } else if (i < 49152) {
        int j = i - 32768;
        int n = j >> 7, k = j & 127;
        v = W2[(size_t)k * 128 + n];
        o = swb(n, 2 * k); dst = g_W2f_;
    } else {
        int j = i - 49152;
        int q = j >> 15; j &= 32767;
        int n = j >> 7, k = j & 127;
        const float* W = q ? Wg : W1;
        v = (n < 128) ? W[(size_t)k * 128 + n]
                      : W[(size_t)(128 + k) * 128 + (n - 128)];
        o = swb(n, 2 * k); dst = g_BNf_[q];
    }
    *(__half*)(dst + o) = __float2half_rn(v);
}

// ============================================================================
// Node kernel: 512 threads, 256-node tiles, ldmatrix fragment loads,
// t-grouped (q/t-swapped) g_T output.  smem: B 64K | AH 64K = 131072
// ============================================================================
__global__ __launch_bounds__(512, 1)
void node_mma_kernel(const float* __restrict__ x)
{
    extern __shared__ char sm[];
    char* B  = sm;
    char* AH = sm + 65536;

    const int tid = threadIdx.x;
    const int w = tid >> 5, lane = tid & 31;
    const int g = lane >> 2, t = lane & 3;
    const int lr = w * 16 + g;

    const int mid = lane >> 3, rr = lane & 7;
    const int aRowOff = (mid & 1) * 8 + rr;
    const int aHs = (mid >> 1) * 16;
    const int bNoff = (mid >> 1) * 8 + rr;
    const int bHs = (mid & 1) * 16;
    const uint32_t rx = (uint32_t)(rr << 4);
    const uint32_t Bu = smem_u32(B);
    const uint32_t aBase = smem_u32(AH) + (uint32_t)(w * 16 + aRowOff) * 256;

    for (int q = 0; q < 2; q++) {
        __syncthreads();
        for (int i = tid; i < 4096; i += 512)
            ((float4*)B)[i] = ((const float4*)g_BNf_[q])[i];
        __syncthreads();

        for (int tile = blockIdx.x; tile < NODE_TILES; tile += gridDim.x) {
            #pragma unroll
            for (int i = 0; i < 16; i++) {
                int r = w * 16 + i;
                int node = tile * 256 + r;
                float4 v = (node < NN) ? *(const float4*)(x + (size_t)node * 128 + lane * 4)
                                       : make_float4(0.f, 0.f, 0.f, 0.f);
                __half2 h0 = __floats2half2_rn(v.x, v.y);
                __half2 h1 = __floats2half2_rn(v.z, v.w);
                *(uint2*)(AH + swb(r, 8 * lane)) =
                    make_uint2(*(uint32_t*)&h0, *(uint32_t*)&h1);
            }
            __syncwarp();

            const int n1 = tile * 256 + lr;
            const int n2 = n1 + 8;
            #pragma unroll
            for (int nh = 0; nh < 2; nh++) {
                float acc[16][4];
                #pragma unroll
                for (int j = 0; j < 16; j++)
                    #pragma unroll
                    for (int c = 0; c < 4; c++) acc[j][c] = 0.f;
                #pragma unroll
                for (int s = 0; s < 8; s++) {
                    uint32_t a[4];
                    ldm_x4(a, aBase + (((uint32_t)(32 * s + aHs)) ^ rx));
                    #pragma unroll
                    for (int jp = 0; jp < 8; jp++) {
                        uint32_t b[4];
                        int n = nh * 128 + jp * 16 + bNoff;
                        ldm_x4(b, Bu + (uint32_t)n * 256 + (((uint32_t)(32 * s + bHs)) ^ rx));
                        mma16816h(acc[2 * jp],     a[0], a[1], a[2], a[3], b[0], b[1]);
                        mma16816h(acc[2 * jp + 1], a[0], a[1], a[2], a[3], b[2], b[3]);
                    }
                }
                // q/t-swapped t-grouped store: chunk q4 at q4*64 + t*16
                const size_t secoff = (size_t)(q * 256 + nh * 128) * 2 + (size_t)t * 16;
                #pragma unroll
                for (int e2s = 0; e2s < 2; e2s++) {
                    int n = e2s ? n2 : n1;
                    int c0 = e2s ? 2 : 0;
                    if (n < NN) {
                        char* s1 = (char*)g_T4 + (size_t)n * 1024 + secoff;
                        #pragma unroll
                        for (int q4 = 0; q4 < 4; q4++) {
                            __half2 a0 = __floats2half2_rn(acc[4*q4+0][c0], acc[4*q4+0][c0+1]);
                            __half2 a1 = __floats2half2_rn(acc[4*q4+1][c0], acc[4*q4+1][c0+1]);
                            __half2 a2 = __floats2half2_rn(acc[4*q4+2][c0], acc[4*q4+2][c0+1]);
                            __half2 a3 = __floats2half2_rn(acc[4*q4+3][c0], acc[4*q4+3][c0+1]);
                            *(uint4*)(s1 + 64 * q4) =
                                make_uint4(*(uint32_t*)&a0, *(uint32_t*)&a1,
                                           *(uint32_t*)&a2, *(uint32_t*)&a3);
                        }
                    }
                }
            }
            __syncwarp();
        }
    }
}

// ============================================================================
// Edge kernel: R13 structure + fast transcendentals.
// smem: B1 64K | W2 32K | AH 32K | G 32K | S 2K = 165888
// ============================================================================
__global__ __launch_bounds__(512, 1)
void edge_mma_kernel(const int* __restrict__ ei, const float* __restrict__ ea,
                     const float* __restrict__ b1, const float* __restrict__ g1,
                     const float* __restrict__ be1, const float* __restrict__ b2,
                     const float* __restrict__ bg, const float* __restrict__ gn,
                     const float* __restrict__ bn, float* __restrict__ out,
                     int tile0)
{
    extern __shared__ char sm[];
    char* B1  = sm;
    char* W2s = sm + 65536;
    char* AH  = sm + 98304;
    char* G   = sm + 131072;
    float* S  = (float*)(sm + 163840);

    const int tid = threadIdx.x;
    const int w = tid >> 5, lane = tid & 31;
    const int g = lane >> 2, t = lane & 3;
    const int pw = w & 7;
    const bool isH = (w < 8);
    const int lr = pw * 16 + g;
    const int barid = 1 + pw;

    const int mid = lane >> 3, rr = lane & 7;
    const int aRowOff = (mid & 1) * 8 + rr;
    const int aHs = (mid >> 1) * 16;
    const int bNoff = (mid >> 1) * 8 + rr;
    const int bHs = (mid & 1) * 16;
    const uint32_t rx = (uint32_t)(rr << 4);

    const uint32_t B1u = smem_u32(B1);
    const uint32_t W2u = smem_u32(W2s);
    const uint32_t aBase = smem_u32(AH) + (uint32_t)(pw * 16 + aRowOff) * 256;

    for (int i = tid; i < 4096; i += 512) ((float4*)B1)[i] = ((const float4*)g_B1f_)[i];
    for (int i = tid; i < 2048; i += 512) ((float4*)W2s)[i] = ((const float4*)g_W2f_)[i];
    __syncthreads();

    const int tile_end = tile0 + EDGE_TILES / 4;
    for (int tile = tile0 + blockIdx.x; tile < tile_end; tile += gridDim.x) {
        // ---- indices early ----
        const int e1 = tile * 128 + lr;
        const int e2 = e1 + 8;
        const int is1 = ei[e1], id1 = ei[NE + e1];
        const int is2 = ei[e2], id2 = ei[NE + e2];

        // ---- stage A1 (fp16 ea) ----
        #pragma unroll
        for (int i = 0; i < 8; i++) {
            int r = pw * 16 + (isH ? i : 8 + i);
            float4 v = *(const float4*)(ea + (size_t)(tile * 128 + r) * 128 + lane * 4);
            __half2 h0 = __floats2half2_rn(v.x, v.y);
            __half2 h1 = __floats2half2_rn(v.z, v.w);
            *(uint2*)(AH + swb(r, 8 * lane)) =
                make_uint2(*(uint32_t*)&h0, *(uint32_t*)&h1);
        }
        PAIR_BAR(barid);

        // ---- bias init + 64B-contiguous t-grouped gathers ----
        const int offs = isH ? 0 : 512;
        const int offd = isH ? 256 : 768;
        const char* Tb = (const char*)g_T4;
        const char* P1s = Tb + (size_t)is1 * 1024 + offs + t * 16;
        const char* P1d = Tb + (size_t)id1 * 1024 + offd + t * 16;
        const char* P2s = Tb + (size_t)is2 * 1024 + offs + t * 16;
        const char* P2d = Tb + (size_t)id2 * 1024 + offd + t * 16;
        const float* bias = isH ? b1 : bg;

        float acc[16][4];
        #pragma unroll
        for (int j = 0; j < 16; j++) {
            float2 bb = *(const float2*)(bias + j * 8 + 2 * t);
            acc[j][0] = bb.x; acc[j][1] = bb.y;
            acc[j][2] = bb.x; acc[j][3] = bb.y;
        }
        #pragma unroll
        for (int q = 0; q < 4; q++) {
            uint4 u1 = *(const uint4*)(P1s + 64 * q);
            uint4 u2 = *(const uint4*)(P1d + 64 * q);
            uint4 u3 = *(const uint4*)(P2s + 64 * q);
            uint4 u4 = *(const uint4*)(P2d + 64 * q);
            int j0 = 4 * q;
            ACC2(u1.x, j0 + 0, 0) ACC2(u1.y, j0 + 1, 0) ACC2(u1.z, j0 + 2, 0) ACC2(u1.w, j0 + 3, 0)
            ACC2(u2.x, j0 + 0, 0) ACC2(u2.y, j0 + 1, 0) ACC2(u2.z, j0 + 2, 0) ACC2(u2.w, j0 + 3, 0)
            ACC2(u3.x, j0 + 0, 2) ACC2(u3.y, j0 + 1, 2) ACC2(u3.z, j0 + 2, 2) ACC2(u3.w, j0 + 3, 2)
            ACC2(u4.x, j0 + 0, 2) ACC2(u4.y, j0 + 1, 2) ACC2(u4.z, j0 + 2, 2) ACC2(u4.w, j0 + 3, 2)
        }

        // ---- GEMM1 via ldmatrix ----
        const int nbase = isH ? 0 : 128;
        #pragma unroll
        for (int s = 0; s < 8; s++) {
            uint32_t a[4];
            ldm_x4(a, aBase + (((uint32_t)(32 * s + aHs)) ^ rx));
            #pragma unroll
            for (int jp = 0; jp < 8; jp++) {
                uint32_t b[4];
                int n = nbase + jp * 16 + bNoff;
                ldm_x4(b, B1u + (uint32_t)n * 256 + (((uint32_t)(32 * s + bHs)) ^ rx));
                mma16816h(acc[2 * jp],     a[0], a[1], a[2], a[3], b[0], b[1]);
                mma16816h(acc[2 * jp + 1], a[0], a[1], a[2], a[3], b[2], b[3]);
            }
        }

        // ---- per-role nonlinearity (fast transcendentals) ----
        if (isH) {
            float s1 = 0.f, q1 = 0.f, s2 = 0.f, q2 = 0.f;
            #pragma unroll
            for (int j = 0; j < 16; j++) {
                s1 += acc[j][0] + acc[j][1];
                q1 += acc[j][0] * acc[j][0] + acc[j][1] * acc[j][1];
                s2 += acc[j][2] + acc[j][3];
                q2 += acc[j][2] * acc[j][2] + acc[j][3] * acc[j][3];
            }
            #pragma unroll
            for (int o = 1; o <= 2; o <<= 1) {
                s1 += __shfl_xor_sync(0xFFFFFFFFu, s1, o);
                q1 += __shfl_xor_sync(0xFFFFFFFFu, q1, o);
                s2 += __shfl_xor_sync(0xFFFFFFFFu, s2, o);
                q2 += __shfl_xor_sync(0xFFFFFFFFu, q2, o);
            }
            float mu1 = s1 * (1.f / 128.f), rs1 = rsqrtf(q1 * (1.f / 128.f) - mu1 * mu1 + EPSC);
            float mu2 = s2 * (1.f / 128.f), rs2 = rsqrtf(q2 * (1.f / 128.f) - mu2 * mu2 + EPSC);
            #pragma unroll
            for (int j = 0; j < 16; j++) {
                int col = j * 8 + 2 * t;
                float2 gv = *(const float2*)(g1 + col);
                float2 bv = *(const float2*)(be1 + col);
                acc[j][0] = fast_gelu((acc[j][0] - mu1) * rs1 * gv.x + bv.x);
                acc[j][1] = fast_gelu((acc[j][1] - mu1) * rs1 * gv.y + bv.y);
                acc[j][2] = fast_gelu((acc[j][2] - mu2) * rs2 * gv.x + bv.x);
                acc[j][3] = fast_gelu((acc[j][3] - mu2) * rs2 * gv.y + bv.y);
            }
        } else {
            #pragma unroll
            for (int j = 0; j < 16; j++)
                #pragma unroll
                for (int c = 0; c < 4; c++)
                    acc[j][c] = fast_sigmoid(acc[j][c]);
            #pragma unroll
            for (int j = 0; j < 8; j++) {        // sigmoid cols 0..63 -> G
                int col = j * 8 + 2 * t;
                *(float2*)(G + gofs(lr, col))     = make_float2(acc[j][0], acc[j][1]);
                *(float2*)(G + gofs(lr + 8, col)) = make_float2(acc[j][2], acc[j][3]);
            }
        }
        PAIR_BAR(barid);   // A1 reads done; G written

        if (isH) {         // write A2 = gelu(h) fp16
            #pragma unroll
            for (int j = 0; j < 16; j++) {
                __half2 p0 = __floats2half2_rn(acc[j][0], acc[j][1]);
                __half2 p1 = __floats2half2_rn(acc[j][2], acc[j][3]);
                int b = 16 * j + 4 * t;
                *(uint32_t*)(AH + swb(lr, b))     = *(uint32_t*)&p0;
                *(uint32_t*)(AH + swb(lr + 8, b)) = *(uint32_t*)&p1;
            }
        }
        PAIR_BAR(barid);   // A2 visible

        // ---- preload ea residual (consumed after GEMM2) ----
        const int nb2 = isH ? 0 : 64;
        float2 eAv[8], eBv[8];
        #pragma unroll
        for (int jl = 0; jl < 8; jl++) {
            int col = nb2 + jl * 8 + 2 * t;
            eAv[jl] = *(const float2*)(ea + (size_t)e1 * 128 + col);
            eBv[jl] = *(const float2*)(ea + (size_t)e2 * 128 + col);
        }

        // ---- GEMM2 split: h -> n 0..63, gate -> n 64..127 ----
        float acc2[8][4];
        #pragma unroll
        for (int jl = 0; jl < 8; jl++)
            #pragma unroll
            for (int c = 0; c < 4; c++) acc2[jl][c] = 0.f;
        #pragma unroll
        for (int s = 0; s < 8; s++) {
            uint32_t a[4];
            ldm_x4(a, aBase + (((uint32_t)(32 * s + aHs)) ^ rx));
            #pragma unroll
            for (int jp = 0; jp < 4; jp++) {
                uint32_t b[4];
                int n = nb2 + jp * 16 + bNoff;
                ldm_x4(b, W2u + (uint32_t)n * 256 + (((uint32_t)(32 * s + bHs)) ^ rx));
                mma16816h(acc2[2 * jp],     a[0], a[1], a[2], a[3], b[0], b[1]);
                mma16816h(acc2[2 * jp + 1], a[0], a[1], a[2], a[3], b[2], b[3]);
            }
        }

        // ---- epilogue half per warp: r = (h2+b2)*gate + ea ----
        float r[8][4];
        #pragma unroll
        for (int jl = 0; jl < 8; jl++) {
            int col = nb2 + jl * 8 + 2 * t;
            float2 bv = *(const float2*)(b2 + col);
            float g0, g1v, g2, g3;
            if (isH) {
                float2 gA = *(const float2*)(G + gofs(lr, col));
                float2 gB = *(const float2*)(G + gofs(lr + 8, col));
                g0 = gA.x; g1v = gA.y; g2 = gB.x; g3 = gB.y;
            } else {
                g0 = acc[8 + jl][0]; g1v = acc[8 + jl][1];
                g2 = acc[8 + jl][2]; g3 = acc[8 + jl][3];
            }
            r[jl][0] = (acc2[jl][0] + bv.x) * g0 + eAv[jl].x;
            r[jl][1] = (acc2[jl][1] + bv.y) * g1v + eAv[jl].y;
            r[jl][2] = (acc2[jl][2] + bv.x) * g2 + eBv[jl].x;
            r[jl][3] = (acc2[jl][3] + bv.y) * g3 + eBv[jl].y;
        }

        // ---- final LN: partial sums + pair exchange ----
        float s1 = 0.f, q1 = 0.f, s2 = 0.f, q2 = 0.f;
        #pragma unroll
        for (int jl = 0; jl < 8; jl++) {
            s1 += r[jl][0] + r[jl][1];
            q1 += r[jl][0] * r[jl][0] + r[jl][1] * r[jl][1];
            s2 += r[jl][2] + r[jl][3];
            q2 += r[jl][2] * r[jl][2] + r[jl][3] * r[jl][3];
        }
        #pragma unroll
        for (int o = 1; o <= 2; o <<= 1) {
            s1 += __shfl_xor_sync(0xFFFFFFFFu, s1, o);
            q1 += __shfl_xor_sync(0xFFFFFFFFu, q1, o);
            s2 += __shfl_xor_sync(0xFFFFFFFFu, s2, o);
            q2 += __shfl_xor_sync(0xFFFFFFFFu, q2, o);
        }
        {
            float* sp = S + pw * 64 + (isH ? 0 : 32) + g * 4;
            if (t == 0) { sp[0] = s1; sp[1] = q1; sp[2] = s2; sp[3] = q2; }
        }
        PAIR_BAR(barid);
        {
            const float* sp = S + pw * 64 + (isH ? 32 : 0) + g * 4;
            s1 += sp[0]; q1 += sp[1]; s2 += sp[2]; q2 += sp[3];
        }
        float mu1 = s1 * (1.f / 128.f), rs1 = rsqrtf(q1 * (1.f / 128.f) - mu1 * mu1 + EPSC);
        float mu2 = s2 * (1.f / 128.f), rs2 = rsqrtf(q2 * (1.f / 128.f) - mu2 * mu2 + EPSC);
        #pragma unroll
        for (int jl = 0; jl < 8; jl++) {
            int col = nb2 + jl * 8 + 2 * t;
            float2 gv = *(const float2*)(gn + col);
            float2 bv = *(const float2*)(bn + col);
            float2 o1, o2;
            o1.x = (r[jl][0] - mu1) * rs1 * gv.x + bv.x;
            o1.y = (r[jl][1] - mu1) * rs1 * gv.y + bv.y;
            o2.x = (r[jl][2] - mu2) * rs2 * gv.x + bv.x;
            o2.y = (r[jl][3] - mu2) * rs2 * gv.y + bv.y;
            *(float2*)(out + (size_t)e1 * 128 + col) = o1;
            *(float2*)(out + (size_t)e2 * 128 + col) = o2;
        }
    }
}

// ---------------------------------------------------------------------------
extern "C" void kernel_launch(void* const* d_in, const int* in_sizes, int n_in,
                              void* d_out, int out_size)
{
    const float* x   = (const float*)d_in[0];
    const int*   ei  = (const int*)d_in[1];
    const float* ea  = (const float*)d_in[2];
    const float* W1  = (const float*)d_in[3];
    const float* b1  = (const float*)d_in[4];
    const float* g1  = (const float*)d_in[5];
    const float* be1 = (const float*)d_in[6];
    const float* W2  = (const float*)d_in[7];
    const float* b2  = (const float*)d_in[8];
    const float* Wg  = (const float*)d_in[9];
    const float* bg  = (const float*)d_in[10];
    const float* gn  = (const float*)d_in[11];
    const float* bn  = (const float*)d_in[12];
    float*       out = (float*)d_out;

    const int node_smem = 131072;
    const int edge_smem = 165888;
    cudaFuncSetAttribute(node_mma_kernel, cudaFuncAttributeMaxDynamicSharedMemorySize, node_smem);
    cudaFuncSetAttribute(edge_mma_kernel, cudaFuncAttributeMaxDynamicSharedMemorySize, edge_smem);

    prep_kernel<<<448, 256>>>(W1, Wg, W2);
    node_mma_kernel<<<GRID_P, 512, node_smem>>>(x);
    for (int part = 0; part < 4; part++)
        edge_mma_kernel<<<GRID_P, 512, edge_smem>>>(ei, ea, b1, g1, be1, b2, bg, gn, bn,
                                                    out, part * (EDGE_TILES / 4));
}

// round 15
// speedup vs baseline: 1.5735x; 1.0009x over previous
#include <cuda_runtime.h>
#include <cuda_fp16.h>
#include <stdint.h>
#include <math.h>

#define NN 100000
#define NE 524288
#define EPSC 1e-5f
#define EDGE_TILES 4096
#define NODE_TILES 391
#define GRID_P 148
#define SQRT1_2 0.70710678118654752440f

// g_T fp16, t-grouped fragment layout (q/t swapped for 64B-contiguous gathers).
static __device__ uint4 g_T4[(size_t)NN * 64];    // NN * 1024 bytes

// Pre-swizzled fp16 weight images
static __device__ char g_B1f_[65536];      // [W1e|Wge] 256n x 128k
static __device__ char g_W2f_[32768];      // W2 128n x 128k
static __device__ char g_BNf_[2][65536];   // node W1 / Wg, 256n x 128k

// ---------------- helpers ----------------
__device__ __forceinline__ int swb(int row, int b) {
    return row * 256 + (b ^ ((row & 7) << 4));
}
__device__ __forceinline__ int gofs(int row, int col) {
    return row * 256 + ((col * 4) ^ ((row & 7) << 5));
}
__device__ __forceinline__ uint32_t smem_u32(const void* p) {
    uint32_t a;
    asm("{ .reg .u64 t; cvta.to.shared.u64 t, %1; cvt.u32.u64 %0, t; }" : "=r"(a) : "l"(p));
    return a;
}
__device__ __forceinline__ void ldm_x4(uint32_t f[4], uint32_t addr) {
    asm volatile("ldmatrix.sync.aligned.m8n8.x4.shared.b16 {%0,%1,%2,%3}, [%4];"
                 : "=r"(f[0]), "=r"(f[1]), "=r"(f[2]), "=r"(f[3]) : "r"(addr));
}
__device__ __forceinline__ void mma16816h(float* c, uint32_t a0, uint32_t a1, uint32_t a2,
                                          uint32_t a3, uint32_t b0, uint32_t b1) {
    asm volatile("mma.sync.aligned.m16n8k16.row.col.f32.f16.f16.f32 "
                 "{%0,%1,%2,%3}, {%4,%5,%6,%7}, {%8,%9}, {%0,%1,%2,%3};"
                 : "+f"(c[0]), "+f"(c[1]), "+f"(c[2]), "+f"(c[3])
                 : "r"(a0), "r"(a1), "r"(a2), "r"(a3), "r"(b0), "r"(b1));
}
__device__ __forceinline__ float fast_sigmoid(float x) {
    return __fdividef(1.f, 1.f + __expf(-x));
}
__device__ __forceinline__ float fast_erf(float z) {
    float az = fabsf(z);
    float t  = __fdividef(1.f, fmaf(0.3275911f, az, 1.f));
    float p  = fmaf(1.061405429f, t, -1.453152027f);
    p = fmaf(p, t, 1.421413741f);
    p = fmaf(p, t, -0.284496736f);
    p = fmaf(p, t, 0.254829592f);
    p *= t;
    float r = 1.f - p * __expf(-az * az);
    return copysignf(r, z);
}
__device__ __forceinline__ float fast_gelu(float y) {
    return 0.5f * y * (1.f + fast_erf(y * SQRT1_2));
}
#define PAIR_BAR(id) asm volatile("bar.sync %0, 64;" :: "r"(id) : "memory")
#define ACC2(vv, jj, c0) { float2 _f = __half22float2(*reinterpret_cast<const __half2*>(&(vv))); \
                           acc[jj][c0] += _f.x; acc[jj][(c0) + 1] += _f.y; }

// ============================================================================
// Prep kernel
// ============================================================================
__global__ void prep_kernel(const float* __restrict__ W1,
                            const float* __restrict__ Wg,
                            const float* __restrict__ W2)
{
    int i = blockIdx.x * 256 + threadIdx.x;
    float v;
    char* dst;
    int o;
    if (i < 32768) {
        int n = i >> 7, k = i & 127;
        v = (n < 128) ? W1[(size_t)(256 + k) * 128 + n]
                      : Wg[(size_t)(256 + k) * 128 + (n - 128)];
        o = swb(n, 2 * k); dst = g_B1f_;
    } else if (i < 49152) {
        int j = i - 32768;
        int n = j >> 7, k = j & 127;
        v = W2[(size_t)k * 128 + n];
        o = swb(n, 2 * k); dst = g_W2f_;
    } else {
        int j = i - 49152;
        int q = j >> 15; j &= 32767;
        int n = j >> 7, k = j & 127;
        const float* W = q ? Wg : W1;
        v = (n < 128) ? W[(size_t)k * 128 + n]
                      : W[(size_t)(128 + k) * 128 + (n - 128)];
        o = swb(n, 2 * k); dst = g_BNf_[q];
    }
    *(__half*)(dst + o) = __float2half_rn(v);
}

// ============================================================================
// Node kernel: 512 threads, 256-node tiles, ldmatrix loads, t-grouped output.
// smem: B 64K | AH 64K = 131072
// ============================================================================
__global__ __launch_bounds__(512, 1)
void node_mma_kernel(const float* __restrict__ x)
{
    extern __shared__ char sm[];
    char* B  = sm;
    char* AH = sm + 65536;

    const int tid = threadIdx.x;
    const int w = tid >> 5, lane = tid & 31;
    const int g = lane >> 2, t = lane & 3;
    const int lr = w * 16 + g;

    const int mid = lane >> 3, rr = lane & 7;
    const int aRowOff = (mid & 1) * 8 + rr;
    const int aHs = (mid >> 1) * 16;
    const int bNoff = (mid >> 1) * 8 + rr;
    const int bHs = (mid & 1) * 16;
    const uint32_t rx = (uint32_t)(rr << 4);
    const uint32_t Bu = smem_u32(B);
    const uint32_t aBase = smem_u32(AH) + (uint32_t)(w * 16 + aRowOff) * 256;

    for (int q = 0; q < 2; q++) {
        __syncthreads();
        for (int i = tid; i < 4096; i += 512)
            ((float4*)B)[i] = ((const float4*)g_BNf_[q])[i];
        __syncthreads();

        for (int tile = blockIdx.x; tile < NODE_TILES; tile += gridDim.x) {
            #pragma unroll
            for (int i = 0; i < 16; i++) {
                int r = w * 16 + i;
                int node = tile * 256 + r;
                float4 v = (node < NN) ? *(const float4*)(x + (size_t)node * 128 + lane * 4)
                                       : make_float4(0.f, 0.f, 0.f, 0.f);
                __half2 h0 = __floats2half2_rn(v.x, v.y);
                __half2 h1 = __floats2half2_rn(v.z, v.w);
                *(uint2*)(AH + swb(r, 8 * lane)) =
                    make_uint2(*(uint32_t*)&h0, *(uint32_t*)&h1);
            }
            __syncwarp();

            const int n1 = tile * 256 + lr;
            const int n2 = n1 + 8;
            #pragma unroll
            for (int nh = 0; nh < 2; nh++) {
                float acc[16][4];
                #pragma unroll
                for (int j = 0; j < 16; j++)
                    #pragma unroll
                    for (int c = 0; c < 4; c++) acc[j][c] = 0.f;
                #pragma unroll
                for (int s = 0; s < 8; s++) {
                    uint32_t a[4];
                    ldm_x4(a, aBase + (((uint32_t)(32 * s + aHs)) ^ rx));
                    #pragma unroll
                    for (int jp = 0; jp < 8; jp++) {
                        uint32_t b[4];
                        int n = nh * 128 + jp * 16 + bNoff;
                        ldm_x4(b, Bu + (uint32_t)n * 256 + (((uint32_t)(32 * s + bHs)) ^ rx));
                        mma16816h(acc[2 * jp],     a[0], a[1], a[2], a[3], b[0], b[1]);
                        mma16816h(acc[2 * jp + 1], a[0], a[1], a[2], a[3], b[2], b[3]);
                    }
                }
                const size_t secoff = (size_t)(q * 256 + nh * 128) * 2 + (size_t)t * 16;
                #pragma unroll
                for (int e2s = 0; e2s < 2; e2s++) {
                    int n = e2s ? n2 : n1;
                    int c0 = e2s ? 2 : 0;
                    if (n < NN) {
                        char* s1 = (char*)g_T4 + (size_t)n * 1024 + secoff;
                        #pragma unroll
                        for (int q4 = 0; q4 < 4; q4++) {
                            __half2 a0 = __floats2half2_rn(acc[4*q4+0][c0], acc[4*q4+0][c0+1]);
                            __half2 a1 = __floats2half2_rn(acc[4*q4+1][c0], acc[4*q4+1][c0+1]);
                            __half2 a2 = __floats2half2_rn(acc[4*q4+2][c0], acc[4*q4+2][c0+1]);
                            __half2 a3 = __floats2half2_rn(acc[4*q4+3][c0], acc[4*q4+3][c0+1]);
                            *(uint4*)(s1 + 64 * q4) =
                                make_uint4(*(uint32_t*)&a0, *(uint32_t*)&a1,
                                           *(uint32_t*)&a2, *(uint32_t*)&a3);
                        }
                    }
                }
            }
            __syncwarp();
        }
    }
}

// ============================================================================
// Edge kernel: R14 + gathers-first + separate A2 + fp16 smem residual.
// smem: B1 64K | W2 32K | A1 32K | A2 32K | G 32K | S 2K = 198656
// ============================================================================
__global__ __launch_bounds__(512, 1)
void edge_mma_kernel(const int* __restrict__ ei, const float* __restrict__ ea,
                     const float* __restrict__ b1, const float* __restrict__ g1,
                     const float* __restrict__ be1, const float* __restrict__ b2,
                     const float* __restrict__ bg, const float* __restrict__ gn,
                     const float* __restrict__ bn, float* __restrict__ out,
                     int tile0)
{
    extern __shared__ char sm[];
    char* B1  = sm;
    char* W2s = sm + 65536;
    char* A1  = sm + 98304;
    char* A2  = sm + 131072;
    char* G   = sm + 163840;
    float* S  = (float*)(sm + 196608);

    const int tid = threadIdx.x;
    const int w = tid >> 5, lane = tid & 31;
    const int g = lane >> 2, t = lane & 3;
    const int pw = w & 7;
    const bool isH = (w < 8);
    const int lr = pw * 16 + g;
    const int barid = 1 + pw;

    const int mid = lane >> 3, rr = lane & 7;
    const int aRowOff = (mid & 1) * 8 + rr;
    const int aHs = (mid >> 1) * 16;
    const int bNoff = (mid >> 1) * 8 + rr;
    const int bHs = (mid & 1) * 16;
    const uint32_t rx = (uint32_t)(rr << 4);

    const uint32_t B1u = smem_u32(B1);
    const uint32_t W2u = smem_u32(W2s);
    const uint32_t aBase1 = smem_u32(A1) + (uint32_t)(pw * 16 + aRowOff) * 256;
    const uint32_t aBase2 = smem_u32(A2) + (uint32_t)(pw * 16 + aRowOff) * 256;

    for (int i = tid; i < 4096; i += 512) ((float4*)B1)[i] = ((const float4*)g_B1f_)[i];
    for (int i = tid; i < 2048; i += 512) ((float4*)W2s)[i] = ((const float4*)g_W2f_)[i];
    __syncthreads();

    const int tile_end = tile0 + EDGE_TILES / 4;
    for (int tile = tile0 + blockIdx.x; tile < tile_end; tile += gridDim.x) {
        // ---- indices + gather LDGs issued FIRST (overlap staging latency) ----
        const int e1 = tile * 128 + lr;
        const int e2 = e1 + 8;
        const int is1 = ei[e1], id1 = ei[NE + e1];
        const int is2 = ei[e2], id2 = ei[NE + e2];
        const int offs = isH ? 0 : 512;
        const int offd = isH ? 256 : 768;
        const char* Tb = (const char*)g_T4;
        const char* P1s = Tb + (size_t)is1 * 1024 + offs + t * 16;
        const char* P1d = Tb + (size_t)id1 * 1024 + offd + t * 16;
        const char* P2s = Tb + (size_t)is2 * 1024 + offs + t * 16;
        const char* P2d = Tb + (size_t)id2 * 1024 + offd + t * 16;
        uint4 gv1[4], gv2[4], gv3[4], gv4[4];
        #pragma unroll
        for (int q = 0; q < 4; q++) {
            gv1[q] = *(const uint4*)(P1s + 64 * q);
            gv2[q] = *(const uint4*)(P1d + 64 * q);
            gv3[q] = *(const uint4*)(P2s + 64 * q);
            gv4[q] = *(const uint4*)(P2d + 64 * q);
        }

        // ---- stage A1 (fp16 ea) ----
        #pragma unroll
        for (int i = 0; i < 8; i++) {
            int r = pw * 16 + (isH ? i : 8 + i);
            float4 v = *(const float4*)(ea + (size_t)(tile * 128 + r) * 128 + lane * 4);
            __half2 h0 = __floats2half2_rn(v.x, v.y);
            __half2 h1 = __floats2half2_rn(v.z, v.w);
            *(uint2*)(A1 + swb(r, 8 * lane)) =
                make_uint2(*(uint32_t*)&h0, *(uint32_t*)&h1);
        }
        PAIR_BAR(barid);

        // ---- bias init + fold gathers ----
        const float* bias = isH ? b1 : bg;
        float acc[16][4];
        #pragma unroll
        for (int j = 0; j < 16; j++) {
            float2 bb = *(const float2*)(bias + j * 8 + 2 * t);
            acc[j][0] = bb.x; acc[j][1] = bb.y;
            acc[j][2] = bb.x; acc[j][3] = bb.y;
        }
        #pragma unroll
        for (int q = 0; q < 4; q++) {
            int j0 = 4 * q;
            ACC2(gv1[q].x, j0 + 0, 0) ACC2(gv1[q].y, j0 + 1, 0) ACC2(gv1[q].z, j0 + 2, 0) ACC2(gv1[q].w, j0 + 3, 0)
            ACC2(gv2[q].x, j0 + 0, 0) ACC2(gv2[q].y, j0 + 1, 0) ACC2(gv2[q].z, j0 + 2, 0) ACC2(gv2[q].w, j0 + 3, 0)
            ACC2(gv3[q].x, j0 + 0, 2) ACC2(gv3[q].y, j0 + 1, 2) ACC2(gv3[q].z, j0 + 2, 2) ACC2(gv3[q].w, j0 + 3, 2)
            ACC2(gv4[q].x, j0 + 0, 2) ACC2(gv4[q].y, j0 + 1, 2) ACC2(gv4[q].z, j0 + 2, 2) ACC2(gv4[q].w, j0 + 3, 2)
        }

        // ---- GEMM1 via ldmatrix (A from A1) ----
        const int nbase = isH ? 0 : 128;
        #pragma unroll
        for (int s = 0; s < 8; s++) {
            uint32_t a[4];
            ldm_x4(a, aBase1 + (((uint32_t)(32 * s + aHs)) ^ rx));
            #pragma unroll
            for (int jp = 0; jp < 8; jp++) {
                uint32_t b[4];
                int n = nbase + jp * 16 + bNoff;
                ldm_x4(b, B1u + (uint32_t)n * 256 + (((uint32_t)(32 * s + bHs)) ^ rx));
                mma16816h(acc[2 * jp],     a[0], a[1], a[2], a[3], b[0], b[1]);
                mma16816h(acc[2 * jp + 1], a[0], a[1], a[2], a[3], b[2], b[3]);
            }
        }

        // ---- per-role nonlinearity ----
        if (isH) {
            float s1 = 0.f, q1 = 0.f, s2 = 0.f, q2 = 0.f;
            #pragma unroll
            for (int j = 0; j < 16; j++) {
                s1 += acc[j][0] + acc[j][1];
                q1 += acc[j][0] * acc[j][0] + acc[j][1] * acc[j][1];
                s2 += acc[j][2] + acc[j][3];
                q2 += acc[j][2] * acc[j][2] + acc[j][3] * acc[j][3];
            }
            #pragma unroll
            for (int o = 1; o <= 2; o <<= 1) {
                s1 += __shfl_xor_sync(0xFFFFFFFFu, s1, o);
                q1 += __shfl_xor_sync(0xFFFFFFFFu, q1, o);
                s2 += __shfl_xor_sync(0xFFFFFFFFu, s2, o);
                q2 += __shfl_xor_sync(0xFFFFFFFFu, q2, o);
            }
            float mu1 = s1 * (1.f / 128.f), rs1 = rsqrtf(q1 * (1.f / 128.f) - mu1 * mu1 + EPSC);
            float mu2 = s2 * (1.f / 128.f), rs2 = rsqrtf(q2 * (1.f / 128.f) - mu2 * mu2 + EPSC);
            #pragma unroll
            for (int j = 0; j < 16; j++) {
                int col = j * 8 + 2 * t;
                float2 gv = *(const float2*)(g1 + col);
                float2 bv = *(const float2*)(be1 + col);
                acc[j][0] = fast_gelu((acc[j][0] - mu1) * rs1 * gv.x + bv.x);
                acc[j][1] = fast_gelu((acc[j][1] - mu1) * rs1 * gv.y + bv.y);
                acc[j][2] = fast_gelu((acc[j][2] - mu2) * rs2 * gv.x + bv.x);
                acc[j][3] = fast_gelu((acc[j][3] - mu2) * rs2 * gv.y + bv.y);
            }
        } else {
            #pragma unroll
            for (int j = 0; j < 16; j++)
                #pragma unroll
                for (int c = 0; c < 4; c++)
                    acc[j][c] = fast_sigmoid(acc[j][c]);
            #pragma unroll
            for (int j = 0; j < 8; j++) {
                int col = j * 8 + 2 * t;
                *(float2*)(G + gofs(lr, col))     = make_float2(acc[j][0], acc[j][1]);
                *(float2*)(G + gofs(lr + 8, col)) = make_float2(acc[j][2], acc[j][3]);
            }
        }

        if (isH) {         // write A2 = gelu(h) fp16 into its own region
            #pragma unroll
            for (int j = 0; j < 16; j++) {
                __half2 p0 = __floats2half2_rn(acc[j][0], acc[j][1]);
                __half2 p1 = __floats2half2_rn(acc[j][2], acc[j][3]);
                int b = 16 * j + 4 * t;
                *(uint32_t*)(A2 + swb(lr, b))     = *(uint32_t*)&p0;
                *(uint32_t*)(A2 + swb(lr + 8, b)) = *(uint32_t*)&p1;
            }
        }
        PAIR_BAR(barid);   // A2 + G visible

        // ---- GEMM2 split: h -> n 0..63, gate -> n 64..127 (A from A2) ----
        const int nb2 = isH ? 0 : 64;
        float acc2[8][4];
        #pragma unroll
        for (int jl = 0; jl < 8; jl++)
            #pragma unroll
            for (int c = 0; c < 4; c++) acc2[jl][c] = 0.f;
        #pragma unroll
        for (int s = 0; s < 8; s++) {
            uint32_t a[4];
            ldm_x4(a, aBase2 + (((uint32_t)(32 * s + aHs)) ^ rx));
            #pragma unroll
            for (int jp = 0; jp < 4; jp++) {
                uint32_t b[4];
                int n = nb2 + jp * 16 + bNoff;
                ldm_x4(b, W2u + (uint32_t)n * 256 + (((uint32_t)(32 * s + bHs)) ^ rx));
                mma16816h(acc2[2 * jp],     a[0], a[1], a[2], a[3], b[0], b[1]);
                mma16816h(acc2[2 * jp + 1], a[0], a[1], a[2], a[3], b[2], b[3]);
            }
        }

        // ---- epilogue half per warp: r = (h2+b2)*gate + ea(fp16 from A1) ----
        float r[8][4];
        #pragma unroll
        for (int jl = 0; jl < 8; jl++) {
            int col = nb2 + jl * 8 + 2 * t;
            float2 bv = *(const float2*)(b2 + col);
            uint32_t ha = *(const uint32_t*)(A1 + swb(lr, 2 * col));
            uint32_t hb = *(const uint32_t*)(A1 + swb(lr + 8, 2 * col));
            float2 eA = __half22float2(*reinterpret_cast<const __half2*>(&ha));
            float2 eB = __half22float2(*reinterpret_cast<const __half2*>(&hb));
            float g0, g1v, g2, g3;
            if (isH) {
                float2 gA = *(const float2*)(G + gofs(lr, col));
                float2 gB = *(const float2*)(G + gofs(lr + 8, col));
                g0 = gA.x; g1v = gA.y; g2 = gB.x; g3 = gB.y;
            } else {
                g0 = acc[8 + jl][0]; g1v = acc[8 + jl][1];
                g2 = acc[8 + jl][2]; g3 = acc[8 + jl][3];
            }
            r[jl][0] = (acc2[jl][0] + bv.x) * g0 + eA.x;
            r[jl][1] = (acc2[jl][1] + bv.y) * g1v + eA.y;
            r[jl][2] = (acc2[jl][2] + bv.x) * g2 + eB.x;
            r[jl][3] = (acc2[jl][3] + bv.y) * g3 + eB.y;
        }

        // ---- final LN: partial sums + pair exchange ----
        float s1 = 0.f, q1 = 0.f, s2 = 0.f, q2 = 0.f;
        #pragma unroll
        for (int jl = 0; jl < 8; jl++) {
            s1 += r[jl][0] + r[jl][1];
            q1 += r[jl][0] * r[jl][0] + r[jl][1] * r[jl][1];
            s2 += r[jl][2] + r[jl][3];
            q2 += r[jl][2] * r[jl][2] + r[jl][3] * r[jl][3];
        }
        #pragma unroll
        for (int o = 1; o <= 2; o <<= 1) {
            s1 += __shfl_xor_sync(0xFFFFFFFFu, s1, o);
            q1 += __shfl_xor_sync(0xFFFFFFFFu, q1, o);
            s2 += __shfl_xor_sync(0xFFFFFFFFu, s2, o);
            q2 += __shfl_xor_sync(0xFFFFFFFFu, q2, o);
        }
        {
            float* sp = S + pw * 64 + (isH ? 0 : 32) + g * 4;
            if (t == 0) { sp[0] = s1; sp[1] = q1; sp[2] = s2; sp[3] = q2; }
        }
        PAIR_BAR(barid);   // also: A1/G reads complete -> safe to restage next tile
        {
            const float* sp = S + pw * 64 + (isH ? 32 : 0) + g * 4;
            s1 += sp[0]; q1 += sp[1]; s2 += sp[2]; q2 += sp[3];
        }
        float mu1 = s1 * (1.f / 128.f), rs1 = rsqrtf(q1 * (1.f / 128.f) - mu1 * mu1 + EPSC);
        float mu2 = s2 * (1.f / 128.f), rs2 = rsqrtf(q2 * (1.f / 128.f) - mu2 * mu2 + EPSC);
        #pragma unroll
        for (int jl = 0; jl < 8; jl++) {
            int col = nb2 + jl * 8 + 2 * t;
            float2 gv = *(const float2*)(gn + col);
            float2 bv = *(const float2*)(bn + col);
            float2 o1, o2;
            o1.x = (r[jl][0] - mu1) * rs1 * gv.x + bv.x;
            o1.y = (r[jl][1] - mu1) * rs1 * gv.y + bv.y;
            o2.x = (r[jl][2] - mu2) * rs2 * gv.x + bv.x;
            o2.y = (r[jl][3] - mu2) * rs2 * gv.y + bv.y;
            *(float2*)(out + (size_t)e1 * 128 + col) = o1;
            *(float2*)(out + (size_t)e2 * 128 + col) = o2;
        }
    }
}

// ---------------------------------------------------------------------------
extern "C" void kernel_launch(void* const* d_in, const int* in_sizes, int n_in,
                              void* d_out, int out_size)
{
    const float* x   = (const float*)d_in[0];
    const int*   ei  = (const int*)d_in[1];
    const float* ea  = (const float*)d_in[2];
    const float* W1  = (const float*)d_in[3];
    const float* b1  = (const float*)d_in[4];
    const float* g1  = (const float*)d_in[5];
    const float* be1 = (const float*)d_in[6];
    const float* W2  = (const float*)d_in[7];
    const float* b2  = (const float*)d_in[8];
    const float* Wg  = (const float*)d_in[9];
    const float* bg  = (const float*)d_in[10];
    const float* gn  = (const float*)d_in[11];
    const float* bn  = (const float*)d_in[12];
    float*       out = (float*)d_out;

    const int node_smem = 131072;
    const int edge_smem = 198656;
    cudaFuncSetAttribute(node_mma_kernel, cudaFuncAttributeMaxDynamicSharedMemorySize, node_smem);
    cudaFuncSetAttribute(edge_mma_kernel, cudaFuncAttributeMaxDynamicSharedMemorySize, edge_smem);

    prep_kernel<<<448, 256>>>(W1, Wg, W2);
    node_mma_kernel<<<GRID_P, 512, node_smem>>>(x);
    for (int part = 0; part < 4; part++)
        edge_mma_kernel<<<GRID_P, 512, edge_smem>>>(ei, ea, b1, g1, be1, b2, bg, gn, bn,
                                                    out, part * (EDGE_TILES / 4));
}

// round 16
// speedup vs baseline: 1.8215x; 1.1576x over previous
#include <cuda_runtime.h>
#include <cuda_fp16.h>
#include <stdint.h>
#include <math.h>

#define NN 100000
#define NE 524288
#define EPSC 1e-5f
#define EDGE_TILES 4096
#define NODE_TILES 391
#define GRID_P 148
#define SQRT1_2 0.70710678118654752440f

// g_T fp16, t-grouped fragment layout (q/t swapped for 64B-contiguous gathers).
static __device__ uint4 g_T4[(size_t)NN * 64];    // NN * 1024 bytes

// Pre-swizzled fp16 weight images
static __device__ char g_B1f_[65536];      // [W1e|Wge] 256n x 128k
static __device__ char g_W2f_[32768];      // W2 128n x 128k
static __device__ char g_BNf_[2][65536];   // node W1 / Wg, 256n x 128k

// ---------------- helpers ----------------
__device__ __forceinline__ int swb(int row, int b) {
    return row * 256 + (b ^ ((row & 7) << 4));
}
__device__ __forceinline__ int gofs(int row, int col) {
    return row * 256 + ((col * 4) ^ ((row & 7) << 5));
}
__device__ __forceinline__ uint32_t smem_u32(const void* p) {
    uint32_t a;
    asm("{ .reg .u64 t; cvta.to.shared.u64 t, %1; cvt.u32.u64 %0, t; }" : "=r"(a) : "l"(p));
    return a;
}
__device__ __forceinline__ void ldm_x4(uint32_t f[4], uint32_t addr) {
    asm volatile("ldmatrix.sync.aligned.m8n8.x4.shared.b16 {%0,%1,%2,%3}, [%4];"
                 : "=r"(f[0]), "=r"(f[1]), "=r"(f[2]), "=r"(f[3]) : "r"(addr));
}
__device__ __forceinline__ void mma16816h(float* c, uint32_t a0, uint32_t a1, uint32_t a2,
                                          uint32_t a3, uint32_t b0, uint32_t b1) {
    asm volatile("mma.sync.aligned.m16n8k16.row.col.f32.f16.f16.f32 "
                 "{%0,%1,%2,%3}, {%4,%5,%6,%7}, {%8,%9}, {%0,%1,%2,%3};"
                 : "+f"(c[0]), "+f"(c[1]), "+f"(c[2]), "+f"(c[3])
                 : "r"(a0), "r"(a1), "r"(a2), "r"(a3), "r"(b0), "r"(b1));
}
__device__ __forceinline__ float fast_sigmoid(float x) {
    return __fdividef(1.f, 1.f + __expf(-x));
}
__device__ __forceinline__ float fast_erf(float z) {
    float az = fabsf(z);
    float t  = __fdividef(1.f, fmaf(0.3275911f, az, 1.f));
    float p  = fmaf(1.061405429f, t, -1.453152027f);
    p = fmaf(p, t, 1.421413741f);
    p = fmaf(p, t, -0.284496736f);
    p = fmaf(p, t, 0.254829592f);
    p *= t;
    float r = 1.f - p * __expf(-az * az);
    return copysignf(r, z);
}
__device__ __forceinline__ float fast_gelu(float y) {
    return 0.5f * y * (1.f + fast_erf(y * SQRT1_2));
}
#define PAIR_BAR(id) asm volatile("bar.sync %0, 64;" :: "r"(id) : "memory")
#define ACC2(vv, jj, c0) { float2 _f = __half22float2(*reinterpret_cast<const __half2*>(&(vv))); \
                           acc[jj][c0] += _f.x; acc[jj][(c0) + 1] += _f.y; }

// ============================================================================
// Prep kernel
// ============================================================================
__global__ void prep_kernel(const float* __restrict__ W1,
                            const float* __restrict__ Wg,
                            const float* __restrict__ W2)
{
    int i = blockIdx.x * 256 + threadIdx.x;
    float v;
    char* dst;
    int o;
    if (i < 32768) {
        int n = i >> 7, k = i & 127;
        v = (n < 128) ? W1[(size_t)(256 + k) * 128 + n]
                      : Wg[(size_t)(256 + k) * 128 + (n - 128)];
        o = swb(n, 2 * k); dst = g_B1f_;
    } else if (i < 49152) {
        int j = i - 32768;
        int n = j >> 7, k = j & 127;
        v = W2[(size_t)k * 128 + n];
        o = swb(n, 2 * k); dst = g_W2f_;
    } else {
        int j = i - 49152;
        int q = j >> 15; j &= 32767;
        int n = j >> 7, k = j & 127;
        const float* W = q ? Wg : W1;
        v = (n < 128) ? W[(size_t)k * 128 + n]
                      : W[(size_t)(128 + k) * 128 + (n - 128)];
        o = swb(n, 2 * k); dst = g_BNf_[q];
    }
    *(__half*)(dst + o) = __float2half_rn(v);
}

// ============================================================================
// Node kernel: unchanged from R15.
// smem: B 64K | AH 64K = 131072
// ============================================================================
__global__ __launch_bounds__(512, 1)
void node_mma_kernel(const float* __restrict__ x)
{
    extern __shared__ char sm[];
    char* B  = sm;
    char* AH = sm + 65536;

    const int tid = threadIdx.x;
    const int w = tid >> 5, lane = tid & 31;
    const int g = lane >> 2, t = lane & 3;

    const int mid = lane >> 3, rr = lane & 7;
    const int aRowOff = (mid & 1) * 8 + rr;
    const int aHs = (mid >> 1) * 16;
    const int bNoff = (mid >> 1) * 8 + rr;
    const int bHs = (mid & 1) * 16;
    const uint32_t rx = (uint32_t)(rr << 4);
    const uint32_t Bu = smem_u32(B);
    const uint32_t aBase = smem_u32(AH) + (uint32_t)(w * 16 + aRowOff) * 256;
    const int lr = w * 16 + g;

    for (int q = 0; q < 2; q++) {
        __syncthreads();
        for (int i = tid; i < 4096; i += 512)
            ((float4*)B)[i] = ((const float4*)g_BNf_[q])[i];
        __syncthreads();

        for (int tile = blockIdx.x; tile < NODE_TILES; tile += gridDim.x) {
            #pragma unroll
            for (int i = 0; i < 16; i++) {
                int r = w * 16 + i;
                int node = tile * 256 + r;
                float4 v = (node < NN) ? *(const float4*)(x + (size_t)node * 128 + lane * 4)
                                       : make_float4(0.f, 0.f, 0.f, 0.f);
                __half2 h0 = __floats2half2_rn(v.x, v.y);
                __half2 h1 = __floats2half2_rn(v.z, v.w);
                *(uint2*)(AH + swb(r, 8 * lane)) =
                    make_uint2(*(uint32_t*)&h0, *(uint32_t*)&h1);
            }
            __syncwarp();

            const int n1 = tile * 256 + lr;
            const int n2 = n1 + 8;
            #pragma unroll
            for (int nh = 0; nh < 2; nh++) {
                float acc[16][4];
                #pragma unroll
                for (int j = 0; j < 16; j++)
                    #pragma unroll
                    for (int c = 0; c < 4; c++) acc[j][c] = 0.f;
                #pragma unroll
                for (int s = 0; s < 8; s++) {
                    uint32_t a[4];
                    ldm_x4(a, aBase + (((uint32_t)(32 * s + aHs)) ^ rx));
                    #pragma unroll
                    for (int jp = 0; jp < 8; jp++) {
                        uint32_t b[4];
                        int n = nh * 128 + jp * 16 + bNoff;
                        ldm_x4(b, Bu + (uint32_t)n * 256 + (((uint32_t)(32 * s + bHs)) ^ rx));
                        mma16816h(acc[2 * jp],     a[0], a[1], a[2], a[3], b[0], b[1]);
                        mma16816h(acc[2 * jp + 1], a[0], a[1], a[2], a[3], b[2], b[3]);
                    }
                }
                const size_t secoff = (size_t)(q * 256 + nh * 128) * 2 + (size_t)t * 16;
                #pragma unroll
                for (int e2s = 0; e2s < 2; e2s++) {
                    int n = e2s ? n2 : n1;
                    int c0 = e2s ? 2 : 0;
                    if (n < NN) {
                        char* s1 = (char*)g_T4 + (size_t)n * 1024 + secoff;
                        #pragma unroll
                        for (int q4 = 0; q4 < 4; q4++) {
                            __half2 a0 = __floats2half2_rn(acc[4*q4+0][c0], acc[4*q4+0][c0+1]);
                            __half2 a1 = __floats2half2_rn(acc[4*q4+1][c0], acc[4*q4+1][c0+1]);
                            __half2 a2 = __floats2half2_rn(acc[4*q4+2][c0], acc[4*q4+2][c0+1]);
                            __half2 a3 = __floats2half2_rn(acc[4*q4+3][c0], acc[4*q4+3][c0+1]);
                            *(uint4*)(s1 + 64 * q4) =
                                make_uint4(*(uint32_t*)&a0, *(uint32_t*)&a1,
                                           *(uint32_t*)&a2, *(uint32_t*)&a3);
                        }
                    }
                }
            }
            __syncwarp();
        }
    }
}

// ============================================================================
// Edge kernel: R15 + 1-deep ea-staging pipeline (prefetch regs -> late STS).
// smem: B1 64K | W2 32K | A1 32K | A2 32K | G 32K | S 2K = 198656
// ============================================================================
__global__ __launch_bounds__(512, 1)
void edge_mma_kernel(const int* __restrict__ ei, const float* __restrict__ ea,
                     const float* __restrict__ b1, const float* __restrict__ g1,
                     const float* __restrict__ be1, const float* __restrict__ b2,
                     const float* __restrict__ bg, const float* __restrict__ gn,
                     const float* __restrict__ bn, float* __restrict__ out,
                     int tile0)
{
    extern __shared__ char sm[];
    char* B1  = sm;
    char* W2s = sm + 65536;
    char* A1  = sm + 98304;
    char* A2  = sm + 131072;
    char* G   = sm + 163840;
    float* S  = (float*)(sm + 196608);

    const int tid = threadIdx.x;
    const int w = tid >> 5, lane = tid & 31;
    const int g = lane >> 2, t = lane & 3;
    const int pw = w & 7;
    const bool isH = (w < 8);
    const int lr = pw * 16 + g;
    const int barid = 1 + pw;

    const int mid = lane >> 3, rr = lane & 7;
    const int aRowOff = (mid & 1) * 8 + rr;
    const int aHs = (mid >> 1) * 16;
    const int bNoff = (mid >> 1) * 8 + rr;
    const int bHs = (mid & 1) * 16;
    const uint32_t rx = (uint32_t)(rr << 4);

    const uint32_t B1u = smem_u32(B1);
    const uint32_t W2u = smem_u32(W2s);
    const uint32_t aBase1 = smem_u32(A1) + (uint32_t)(pw * 16 + aRowOff) * 256;
    const uint32_t aBase2 = smem_u32(A2) + (uint32_t)(pw * 16 + aRowOff) * 256;

    // staging row for this warp (8 rows per warp within its pair's 16)
    const int stRow0 = pw * 16 + (isH ? 0 : 8);

    for (int i = tid; i < 4096; i += 512) ((float4*)B1)[i] = ((const float4*)g_B1f_)[i];
    for (int i = tid; i < 2048; i += 512) ((float4*)W2s)[i] = ((const float4*)g_W2f_)[i];
    __syncthreads();

    const int tile_end = tile0 + EDGE_TILES / 4;
    const int tfirst = tile0 + blockIdx.x;

    // ---- prologue: stage A1 for the first tile ----
    if (tfirst < tile_end) {
        #pragma unroll
        for (int i = 0; i < 8; i++) {
            int r = stRow0 + i;
            float4 v = *(const float4*)(ea + (size_t)(tfirst * 128 + r) * 128 + lane * 4);
            __half2 h0 = __floats2half2_rn(v.x, v.y);
            __half2 h1 = __floats2half2_rn(v.z, v.w);
            *(uint2*)(A1 + swb(r, 8 * lane)) =
                make_uint2(*(uint32_t*)&h0, *(uint32_t*)&h1);
        }
    }

    for (int tile = tfirst; tile < tile_end; tile += gridDim.x) {
        // ---- gather LDGs issue first; barrier (covers prior STS) overlaps them ----
        const int e1 = tile * 128 + lr;
        const int e2 = e1 + 8;
        const int is1 = ei[e1], id1 = ei[NE + e1];
        const int is2 = ei[e2], id2 = ei[NE + e2];
        const int offs = isH ? 0 : 512;
        const int offd = isH ? 256 : 768;
        const char* Tb = (const char*)g_T4;
        const char* P1s = Tb + (size_t)is1 * 1024 + offs + t * 16;
        const char* P1d = Tb + (size_t)id1 * 1024 + offd + t * 16;
        const char* P2s = Tb + (size_t)is2 * 1024 + offs + t * 16;
        const char* P2d = Tb + (size_t)id2 * 1024 + offd + t * 16;
        uint4 gv1[4], gv2[4], gv3[4], gv4[4];
        #pragma unroll
        for (int q = 0; q < 4; q++) {
            gv1[q] = *(const uint4*)(P1s + 64 * q);
            gv2[q] = *(const uint4*)(P1d + 64 * q);
            gv3[q] = *(const uint4*)(P2s + 64 * q);
            gv4[q] = *(const uint4*)(P2d + 64 * q);
        }
        PAIR_BAR(barid);   // A1 staging (prologue or prev-tile STS) visible

        // ---- bias init + fold gathers ----
        const float* bias = isH ? b1 : bg;
        float acc[16][4];
        #pragma unroll
        for (int j = 0; j < 16; j++) {
            float2 bb = *(const float2*)(bias + j * 8 + 2 * t);
            acc[j][0] = bb.x; acc[j][1] = bb.y;
            acc[j][2] = bb.x; acc[j][3] = bb.y;
        }
        #pragma unroll
        for (int q = 0; q < 4; q++) {
            int j0 = 4 * q;
            ACC2(gv1[q].x, j0 + 0, 0) ACC2(gv1[q].y, j0 + 1, 0) ACC2(gv1[q].z, j0 + 2, 0) ACC2(gv1[q].w, j0 + 3, 0)
            ACC2(gv2[q].x, j0 + 0, 0) ACC2(gv2[q].y, j0 + 1, 0) ACC2(gv2[q].z, j0 + 2, 0) ACC2(gv2[q].w, j0 + 3, 0)
            ACC2(gv3[q].x, j0 + 0, 2) ACC2(gv3[q].y, j0 + 1, 2) ACC2(gv3[q].z, j0 + 2, 2) ACC2(gv3[q].w, j0 + 3, 2)
            ACC2(gv4[q].x, j0 + 0, 2) ACC2(gv4[q].y, j0 + 1, 2) ACC2(gv4[q].z, j0 + 2, 2) ACC2(gv4[q].w, j0 + 3, 2)
        }

        // ---- GEMM1 via ldmatrix (A from A1) ----
        const int nbase = isH ? 0 : 128;
        #pragma unroll
        for (int s = 0; s < 8; s++) {
            uint32_t a[4];
            ldm_x4(a, aBase1 + (((uint32_t)(32 * s + aHs)) ^ rx));
            #pragma unroll
            for (int jp = 0; jp < 8; jp++) {
                uint32_t b[4];
                int n = nbase + jp * 16 + bNoff;
                ldm_x4(b, B1u + (uint32_t)n * 256 + (((uint32_t)(32 * s + bHs)) ^ rx));
                mma16816h(acc[2 * jp],     a[0], a[1], a[2], a[3], b[0], b[1]);
                mma16816h(acc[2 * jp + 1], a[0], a[1], a[2], a[3], b[2], b[3]);
            }
        }

        // ---- per-role nonlinearity ----
        if (isH) {
            float s1 = 0.f, q1 = 0.f, s2 = 0.f, q2 = 0.f;
            #pragma unroll
            for (int j = 0; j < 16; j++) {
                s1 += acc[j][0] + acc[j][1];
                q1 += acc[j][0] * acc[j][0] + acc[j][1] * acc[j][1];
                s2 += acc[j][2] + acc[j][3];
                q2 += acc[j][2] * acc[j][2] + acc[j][3] * acc[j][3];
            }
            #pragma unroll
            for (int o = 1; o <= 2; o <<= 1) {
                s1 += __shfl_xor_sync(0xFFFFFFFFu, s1, o);
                q1 += __shfl_xor_sync(0xFFFFFFFFu, q1, o);
                s2 += __shfl_xor_sync(0xFFFFFFFFu, s2, o);
                q2 += __shfl_xor_sync(0xFFFFFFFFu, q2, o);
            }
            float mu1 = s1 * (1.f / 128.f), rs1 = rsqrtf(q1 * (1.f / 128.f) - mu1 * mu1 + EPSC);
            float mu2 = s2 * (1.f / 128.f), rs2 = rsqrtf(q2 * (1.f / 128.f) - mu2 * mu2 + EPSC);
            #pragma unroll
            for (int j = 0; j < 16; j++) {
                int col = j * 8 + 2 * t;
                float2 gv = *(const float2*)(g1 + col);
                float2 bv = *(const float2*)(be1 + col);
                acc[j][0] = fast_gelu((acc[j][0] - mu1) * rs1 * gv.x + bv.x);
                acc[j][1] = fast_gelu((acc[j][1] - mu1) * rs1 * gv.y + bv.y);
                acc[j][2] = fast_gelu((acc[j][2] - mu2) * rs2 * gv.x + bv.x);
                acc[j][3] = fast_gelu((acc[j][3] - mu2) * rs2 * gv.y + bv.y);
            }
            #pragma unroll
            for (int j = 0; j < 16; j++) {    // write A2 = gelu(h)
                __half2 p0 = __floats2half2_rn(acc[j][0], acc[j][1]);
                __half2 p1 = __floats2half2_rn(acc[j][2], acc[j][3]);
                int b = 16 * j + 4 * t;
                *(uint32_t*)(A2 + swb(lr, b))     = *(uint32_t*)&p0;
                *(uint32_t*)(A2 + swb(lr + 8, b)) = *(uint32_t*)&p1;
            }
        } else {
            #pragma unroll
            for (int j = 0; j < 16; j++)
                #pragma unroll
                for (int c = 0; c < 4; c++)
                    acc[j][c] = fast_sigmoid(acc[j][c]);
            #pragma unroll
            for (int j = 0; j < 8; j++) {
                int col = j * 8 + 2 * t;
                *(float2*)(G + gofs(lr, col))     = make_float2(acc[j][0], acc[j][1]);
                *(float2*)(G + gofs(lr + 8, col)) = make_float2(acc[j][2], acc[j][3]);
            }
        }
        PAIR_BAR(barid);   // A2 + G visible

        // ---- prefetch next tile's ea rows into registers ----
        int tnext = tile + gridDim.x;
        const int tld = (tnext < tile_end) ? tnext : tile;   // clamp (harmless reload)
        float4 ev[8];
        #pragma unroll
        for (int i = 0; i < 8; i++)
            ev[i] = *(const float4*)(ea + (size_t)(tld * 128 + stRow0 + i) * 128 + lane * 4);

        // ---- GEMM2 split: h -> n 0..63, gate -> n 64..127 (A from A2) ----
        const int nb2 = isH ? 0 : 64;
        float acc2[8][4];
        #pragma unroll
        for (int jl = 0; jl < 8; jl++)
            #pragma unroll
            for (int c = 0; c < 4; c++) acc2[jl][c] = 0.f;
        #pragma unroll
        for (int s = 0; s < 8; s++) {
            uint32_t a[4];
            ldm_x4(a, aBase2 + (((uint32_t)(32 * s + aHs)) ^ rx));
            #pragma unroll
            for (int jp = 0; jp < 4; jp++) {
                uint32_t b[4];
                int n = nb2 + jp * 16 + bNoff;
                ldm_x4(b, W2u + (uint32_t)n * 256 + (((uint32_t)(32 * s + bHs)) ^ rx));
                mma16816h(acc2[2 * jp],     a[0], a[1], a[2], a[3], b[0], b[1]);
                mma16816h(acc2[2 * jp + 1], a[0], a[1], a[2], a[3], b[2], b[3]);
            }
        }

        // ---- epilogue half per warp: r = (h2+b2)*gate + ea(fp16 from A1) ----
        float r[8][4];
        #pragma unroll
        for (int jl = 0; jl < 8; jl++) {
            int col = nb2 + jl * 8 + 2 * t;
            float2 bv = *(const float2*)(b2 + col);
            uint32_t ha = *(const uint32_t*)(A1 + swb(lr, 2 * col));
            uint32_t hb = *(const uint32_t*)(A1 + swb(lr + 8, 2 * col));
            float2 eA = __half22float2(*reinterpret_cast<const __half2*>(&ha));
            float2 eB = __half22float2(*reinterpret_cast<const __half2*>(&hb));
            float g0, g1v, g2, g3;
            if (isH) {
                float2 gA = *(const float2*)(G + gofs(lr, col));
                float2 gB = *(const float2*)(G + gofs(lr + 8, col));
                g0 = gA.x; g1v = gA.y; g2 = gB.x; g3 = gB.y;
            } else {
                g0 = acc[8 + jl][0]; g1v = acc[8 + jl][1];
                g2 = acc[8 + jl][2]; g3 = acc[8 + jl][3];
            }
            r[jl][0] = (acc2[jl][0] + bv.x) * g0 + eA.x;
            r[jl][1] = (acc2[jl][1] + bv.y) * g1v + eA.y;
            r[jl][2] = (acc2[jl][2] + bv.x) * g2 + eB.x;
            r[jl][3] = (acc2[jl][3] + bv.y) * g3 + eB.y;
        }

        // ---- final LN: partial sums + pair exchange ----
        float s1 = 0.f, q1 = 0.f, s2 = 0.f, q2 = 0.f;
        #pragma unroll
        for (int jl = 0; jl < 8; jl++) {
            s1 += r[jl][0] + r[jl][1];
            q1 += r[jl][0] * r[jl][0] + r[jl][1] * r[jl][1];
            s2 += r[jl][2] + r[jl][3];
            q2 += r[jl][2] * r[jl][2] + r[jl][3] * r[jl][3];
        }
        #pragma unroll
        for (int o = 1; o <= 2; o <<= 1) {
            s1 += __shfl_xor_sync(0xFFFFFFFFu, s1, o);
            q1 += __shfl_xor_sync(0xFFFFFFFFu, q1, o);
            s2 += __shfl_xor_sync(0xFFFFFFFFu, s2, o);
            q2 += __shfl_xor_sync(0xFFFFFFFFu, q2, o);
        }
        {
            float* sp = S + pw * 64 + (isH ? 0 : 32) + g * 4;
            if (t == 0) { sp[0] = s1; sp[1] = q1; sp[2] = s2; sp[3] = q2; }
        }
        PAIR_BAR(barid);   // S visible; all A1/G reads complete -> A1 writable
        {
            const float* sp = S + pw * 64 + (isH ? 32 : 0) + g * 4;
            s1 += sp[0]; q1 += sp[1]; s2 += sp[2]; q2 += sp[3];
        }
        float mu1 = s1 * (1.f / 128.f), rs1 = rsqrtf(q1 * (1.f / 128.f) - mu1 * mu1 + EPSC);
        float mu2 = s2 * (1.f / 128.f), rs2 = rsqrtf(q2 * (1.f / 128.f) - mu2 * mu2 + EPSC);

        // ---- stage next tile's A1 from prefetched registers (pre-barrier'd
        //      by next iteration's head PAIR_BAR) ----
        #pragma unroll
        for (int i = 0; i < 8; i++) {
            __half2 h0 = __floats2half2_rn(ev[i].x, ev[i].y);
            __half2 h1 = __floats2half2_rn(ev[i].z, ev[i].w);
            *(uint2*)(A1 + swb(stRow0 + i, 8 * lane)) =
                make_uint2(*(uint32_t*)&h0, *(uint32_t*)&h1);
        }

        // ---- finish LN + out stores ----
        #pragma unroll
        for (int jl = 0; jl < 8; jl++) {
            int col = nb2 + jl * 8 + 2 * t;
            float2 gv = *(const float2*)(gn + col);
            float2 bv = *(const float2*)(bn + col);
            float2 o1, o2;
            o1.x = (r[jl][0] - mu1) * rs1 * gv.x + bv.x;
            o1.y = (r[jl][1] - mu1) * rs1 * gv.y + bv.y;
            o2.x = (r[jl][2] - mu2) * rs2 * gv.x + bv.x;
            o2.y = (r[jl][3] - mu2) * rs2 * gv.y + bv.y;
            *(float2*)(out + (size_t)e1 * 128 + col) = o1;
            *(float2*)(out + (size_t)e2 * 128 + col) = o2;
        }
    }
}

// ---------------------------------------------------------------------------
extern "C" void kernel_launch(void* const* d_in, const int* in_sizes, int n_in,
                              void* d_out, int out_size)
{
    const float* x   = (const float*)d_in[0];
    const int*   ei  = (const int*)d_in[1];
    const float* ea  = (const float*)d_in[2];
    const float* W1  = (const float*)d_in[3];
    const float* b1  = (const float*)d_in[4];
    const float* g1  = (const float*)d_in[5];
    const float* be1 = (const float*)d_in[6];
    const float* W2  = (const float*)d_in[7];
    const float* b2  = (const float*)d_in[8];
    const float* Wg  = (const float*)d_in[9];
    const float* bg  = (const float*)d_in[10];
    const float* gn  = (const float*)d_in[11];
    const float* bn  = (const float*)d_in[12];
    float*       out = (float*)d_out;

    const int node_smem = 131072;
    const int edge_smem = 198656;
    cudaFuncSetAttribute(node_mma_kernel, cudaFuncAttributeMaxDynamicSharedMemorySize, node_smem);
    cudaFuncSetAttribute(edge_mma_kernel, cudaFuncAttributeMaxDynamicSharedMemorySize, edge_smem);

    prep_kernel<<<448, 256>>>(W1, Wg, W2);
    node_mma_kernel<<<GRID_P, 512, node_smem>>>(x);
    for (int part = 0; part < 4; part++)
        edge_mma_kernel<<<GRID_P, 512, edge_smem>>>(ei, ea, b1, g1, be1, b2, bg, gn, bn,
                                                    out, part * (EDGE_TILES / 4));
}

// round 17
// speedup vs baseline: 1.9302x; 1.0597x over previous
#include <cuda_runtime.h>
#include <cuda_fp16.h>
#include <stdint.h>
#include <math.h>

#define NN 100000
#define NE 524288
#define EPSC 1e-5f
#define EDGE_TILES 4096
#define NODE_TILES 391
#define GRID_P 148
#define SQRT1_2 0.70710678118654752440f

// g_T fp16, t-grouped fragment layout (q/t swapped for 64B-contiguous gathers).
static __device__ uint4 g_T4[(size_t)NN * 64];    // NN * 1024 bytes

// Pre-swizzled fp16 weight images
static __device__ char g_B1f_[65536];      // [W1e|Wge] 256n x 128k
static __device__ char g_W2f_[32768];      // W2 128n x 128k
static __device__ char g_BNf_[2][65536];   // node W1 / Wg, 256n x 128k

// ---------------- helpers ----------------
__device__ __forceinline__ int swb(int row, int b) {
    return row * 256 + (b ^ ((row & 7) << 4));
}
__device__ __forceinline__ int gofs(int row, int col) {
    return row * 256 + ((col * 4) ^ ((row & 7) << 5));
}
__device__ __forceinline__ uint32_t smem_u32(const void* p) {
    uint32_t a;
    asm("{ .reg .u64 t; cvta.to.shared.u64 t, %1; cvt.u32.u64 %0, t; }" : "=r"(a) : "l"(p));
    return a;
}
__device__ __forceinline__ void ldm_x4(uint32_t f[4], uint32_t addr) {
    asm volatile("ldmatrix.sync.aligned.m8n8.x4.shared.b16 {%0,%1,%2,%3}, [%4];"
                 : "=r"(f[0]), "=r"(f[1]), "=r"(f[2]), "=r"(f[3]) : "r"(addr));
}
__device__ __forceinline__ void mma16816h(float* c, uint32_t a0, uint32_t a1, uint32_t a2,
                                          uint32_t a3, uint32_t b0, uint32_t b1) {
    asm volatile("mma.sync.aligned.m16n8k16.row.col.f32.f16.f16.f32 "
                 "{%0,%1,%2,%3}, {%4,%5,%6,%7}, {%8,%9}, {%0,%1,%2,%3};"
                 : "+f"(c[0]), "+f"(c[1]), "+f"(c[2]), "+f"(c[3])
                 : "r"(a0), "r"(a1), "r"(a2), "r"(a3), "r"(b0), "r"(b1));
}
__device__ __forceinline__ float fast_sigmoid(float x) {
    return __fdividef(1.f, 1.f + __expf(-x));
}
__device__ __forceinline__ float fast_erf(float z) {
    float az = fabsf(z);
    float t  = __fdividef(1.f, fmaf(0.3275911f, az, 1.f));
    float p  = fmaf(1.061405429f, t, -1.453152027f);
    p = fmaf(p, t, 1.421413741f);
    p = fmaf(p, t, -0.284496736f);
    p = fmaf(p, t, 0.254829592f);
    p *= t;
    float r = 1.f - p * __expf(-az * az);
    return copysignf(r, z);
}
__device__ __forceinline__ float fast_gelu(float y) {
    return 0.5f * y * (1.f + fast_erf(y * SQRT1_2));
}
#define PAIR_BAR(id) asm volatile("bar.sync %0, 64;" :: "r"(id) : "memory")
#define ACC2(vv, jj, c0) { float2 _f = __half22float2(*reinterpret_cast<const __half2*>(&(vv))); \
                           acc[jj][c0] += _f.x; acc[jj][(c0) + 1] += _f.y; }

// ============================================================================
// Prep kernel
// ============================================================================
__global__ void prep_kernel(const float* __restrict__ W1,
                            const float* __restrict__ Wg,
                            const float* __restrict__ W2)
{
    int i = blockIdx.x * 256 + threadIdx.x;
    float v;
    char* dst;
    int o;
    if (i < 32768) {
        int n = i >> 7, k = i & 127;
        v = (n < 128) ? W1[(size_t)(256 + k) * 128 + n]
                      : Wg[(size_t)(256 + k) * 128 + (n - 128)];
        o = swb(n, 2 * k); dst = g_B1f_;
    } else if (i < 49152) {
        int j = i - 32768;
        int n = j >> 7, k = j & 127;
        v = W2[(size_t)k * 128 + n];
        o = swb(n, 2 * k); dst = g_W2f_;
    } else {
        int j = i - 49152;
        int q = j >> 15; j &= 32767;
        int n = j >> 7, k = j & 127;
        const float* W = q ? Wg : W1;
        v = (n < 128) ? W[(size_t)k * 128 + n]
                      : W[(size_t)(128 + k) * 128 + (n - 128)];
        o = swb(n, 2 * k); dst = g_BNf_[q];
    }
    *(__half*)(dst + o) = __float2half_rn(v);
}

// ============================================================================
// Node kernel: R16 + streaming loads of x.
// smem: B 64K | AH 64K = 131072
// ============================================================================
__global__ __launch_bounds__(512, 1)
void node_mma_kernel(const float* __restrict__ x)
{
    extern __shared__ char sm[];
    char* B  = sm;
    char* AH = sm + 65536;

    const int tid = threadIdx.x;
    const int w = tid >> 5, lane = tid & 31;
    const int g = lane >> 2, t = lane & 3;

    const int mid = lane >> 3, rr = lane & 7;
    const int aRowOff = (mid & 1) * 8 + rr;
    const int aHs = (mid >> 1) * 16;
    const int bNoff = (mid >> 1) * 8 + rr;
    const int bHs = (mid & 1) * 16;
    const uint32_t rx = (uint32_t)(rr << 4);
    const uint32_t Bu = smem_u32(B);
    const uint32_t aBase = smem_u32(AH) + (uint32_t)(w * 16 + aRowOff) * 256;
    const int lr = w * 16 + g;

    for (int q = 0; q < 2; q++) {
        __syncthreads();
        for (int i = tid; i < 4096; i += 512)
            ((float4*)B)[i] = ((const float4*)g_BNf_[q])[i];
        __syncthreads();

        for (int tile = blockIdx.x; tile < NODE_TILES; tile += gridDim.x) {
            #pragma unroll
            for (int i = 0; i < 16; i++) {
                int r = w * 16 + i;
                int node = tile * 256 + r;
                float4 v = (node < NN)
                    ? __ldcs((const float4*)(x + (size_t)node * 128 + lane * 4))
                    : make_float4(0.f, 0.f, 0.f, 0.f);
                __half2 h0 = __floats2half2_rn(v.x, v.y);
                __half2 h1 = __floats2half2_rn(v.z, v.w);
                *(uint2*)(AH + swb(r, 8 * lane)) =
                    make_uint2(*(uint32_t*)&h0, *(uint32_t*)&h1);
            }
            __syncwarp();

            const int n1 = tile * 256 + lr;
            const int n2 = n1 + 8;
            #pragma unroll
            for (int nh = 0; nh < 2; nh++) {
                float acc[16][4];
                #pragma unroll
                for (int j = 0; j < 16; j++)
                    #pragma unroll
                    for (int c = 0; c < 4; c++) acc[j][c] = 0.f;
                #pragma unroll
                for (int s = 0; s < 8; s++) {
                    uint32_t a[4];
                    ldm_x4(a, aBase + (((uint32_t)(32 * s + aHs)) ^ rx));
                    #pragma unroll
                    for (int jp = 0; jp < 8; jp++) {
                        uint32_t b[4];
                        int n = nh * 128 + jp * 16 + bNoff;
                        ldm_x4(b, Bu + (uint32_t)n * 256 + (((uint32_t)(32 * s + bHs)) ^ rx));
                        mma16816h(acc[2 * jp],     a[0], a[1], a[2], a[3], b[0], b[1]);
                        mma16816h(acc[2 * jp + 1], a[0], a[1], a[2], a[3], b[2], b[3]);
                    }
                }
                const size_t secoff = (size_t)(q * 256 + nh * 128) * 2 + (size_t)t * 16;
                #pragma unroll
                for (int e2s = 0; e2s < 2; e2s++) {
                    int n = e2s ? n2 : n1;
                    int c0 = e2s ? 2 : 0;
                    if (n < NN) {
                        char* s1 = (char*)g_T4 + (size_t)n * 1024 + secoff;
                        #pragma unroll
                        for (int q4 = 0; q4 < 4; q4++) {
                            __half2 a0 = __floats2half2_rn(acc[4*q4+0][c0], acc[4*q4+0][c0+1]);
                            __half2 a1 = __floats2half2_rn(acc[4*q4+1][c0], acc[4*q4+1][c0+1]);
                            __half2 a2 = __floats2half2_rn(acc[4*q4+2][c0], acc[4*q4+2][c0+1]);
                            __half2 a3 = __floats2half2_rn(acc[4*q4+3][c0], acc[4*q4+3][c0+1]);
                            *(uint4*)(s1 + 64 * q4) =
                                make_uint4(*(uint32_t*)&a0, *(uint32_t*)&a1,
                                           *(uint32_t*)&a2, *(uint32_t*)&a3);
                        }
                    }
                }
            }
            __syncwarp();
        }
    }
}

// ============================================================================
// Edge kernel: R16 pipeline + streaming ea loads / out stores; single launch.
// smem: B1 64K | W2 32K | A1 32K | A2 32K | G 32K | S 2K = 198656
// ============================================================================
__global__ __launch_bounds__(512, 1)
void edge_mma_kernel(const int* __restrict__ ei, const float* __restrict__ ea,
                     const float* __restrict__ b1, const float* __restrict__ g1,
                     const float* __restrict__ be1, const float* __restrict__ b2,
                     const float* __restrict__ bg, const float* __restrict__ gn,
                     const float* __restrict__ bn, float* __restrict__ out)
{
    extern __shared__ char sm[];
    char* B1  = sm;
    char* W2s = sm + 65536;
    char* A1  = sm + 98304;
    char* A2  = sm + 131072;
    char* G   = sm + 163840;
    float* S  = (float*)(sm + 196608);

    const int tid = threadIdx.x;
    const int w = tid >> 5, lane = tid & 31;
    const int g = lane >> 2, t = lane & 3;
    const int pw = w & 7;
    const bool isH = (w < 8);
    const int lr = pw * 16 + g;
    const int barid = 1 + pw;

    const int mid = lane >> 3, rr = lane & 7;
    const int aRowOff = (mid & 1) * 8 + rr;
    const int aHs = (mid >> 1) * 16;
    const int bNoff = (mid >> 1) * 8 + rr;
    const int bHs = (mid & 1) * 16;
    const uint32_t rx = (uint32_t)(rr << 4);

    const uint32_t B1u = smem_u32(B1);
    const uint32_t W2u = smem_u32(W2s);
    const uint32_t aBase1 = smem_u32(A1) + (uint32_t)(pw * 16 + aRowOff) * 256;
    const uint32_t aBase2 = smem_u32(A2) + (uint32_t)(pw * 16 + aRowOff) * 256;

    const int stRow0 = pw * 16 + (isH ? 0 : 8);

    for (int i = tid; i < 4096; i += 512) ((float4*)B1)[i] = ((const float4*)g_B1f_)[i];
    for (int i = tid; i < 2048; i += 512) ((float4*)W2s)[i] = ((const float4*)g_W2f_)[i];
    __syncthreads();

    const int tfirst = blockIdx.x;

    // ---- prologue: stage A1 for the first tile ----
    if (tfirst < EDGE_TILES) {
        #pragma unroll
        for (int i = 0; i < 8; i++) {
            int r = stRow0 + i;
            float4 v = __ldcs((const float4*)(ea + (size_t)(tfirst * 128 + r) * 128 + lane * 4));
            __half2 h0 = __floats2half2_rn(v.x, v.y);
            __half2 h1 = __floats2half2_rn(v.z, v.w);
            *(uint2*)(A1 + swb(r, 8 * lane)) =
                make_uint2(*(uint32_t*)&h0, *(uint32_t*)&h1);
        }
    }

    for (int tile = tfirst; tile < EDGE_TILES; tile += gridDim.x) {
        // ---- gather LDGs issue first; barrier overlaps them ----
        const int e1 = tile * 128 + lr;
        const int e2 = e1 + 8;
        const int is1 = ei[e1], id1 = ei[NE + e1];
        const int is2 = ei[e2], id2 = ei[NE + e2];
        const int offs = isH ? 0 : 512;
        const int offd = isH ? 256 : 768;
        const char* Tb = (const char*)g_T4;
        const char* P1s = Tb + (size_t)is1 * 1024 + offs + t * 16;
        const char* P1d = Tb + (size_t)id1 * 1024 + offd + t * 16;
        const char* P2s = Tb + (size_t)is2 * 1024 + offs + t * 16;
        const char* P2d = Tb + (size_t)id2 * 1024 + offd + t * 16;
        uint4 gv1[4], gv2[4], gv3[4], gv4[4];
        #pragma unroll
        for (int q = 0; q < 4; q++) {
            gv1[q] = *(const uint4*)(P1s + 64 * q);
            gv2[q] = *(const uint4*)(P1d + 64 * q);
            gv3[q] = *(const uint4*)(P2s + 64 * q);
            gv4[q] = *(const uint4*)(P2d + 64 * q);
        }
        PAIR_BAR(barid);   // A1 staging (prologue or prev-tile STS) visible

        // ---- bias init + fold gathers ----
        const float* bias = isH ? b1 : bg;
        float acc[16][4];
        #pragma unroll
        for (int j = 0; j < 16; j++) {
            float2 bb = *(const float2*)(bias + j * 8 + 2 * t);
            acc[j][0] = bb.x; acc[j][1] = bb.y;
            acc[j][2] = bb.x; acc[j][3] = bb.y;
        }
        #pragma unroll
        for (int q = 0; q < 4; q++) {
            int j0 = 4 * q;
            ACC2(gv1[q].x, j0 + 0, 0) ACC2(gv1[q].y, j0 + 1, 0) ACC2(gv1[q].z, j0 + 2, 0) ACC2(gv1[q].w, j0 + 3, 0)
            ACC2(gv2[q].x, j0 + 0, 0) ACC2(gv2[q].y, j0 + 1, 0) ACC2(gv2[q].z, j0 + 2, 0) ACC2(gv2[q].w, j0 + 3, 0)
            ACC2(gv3[q].x, j0 + 0, 2) ACC2(gv3[q].y, j0 + 1, 2) ACC2(gv3[q].z, j0 + 2, 2) ACC2(gv3[q].w, j0 + 3, 2)
            ACC2(gv4[q].x, j0 + 0, 2) ACC2(gv4[q].y, j0 + 1, 2) ACC2(gv4[q].z, j0 + 2, 2) ACC2(gv4[q].w, j0 + 3, 2)
        }

        // ---- GEMM1 via ldmatrix (A from A1) ----
        const int nbase = isH ? 0 : 128;
        #pragma unroll
        for (int s = 0; s < 8; s++) {
            uint32_t a[4];
            ldm_x4(a, aBase1 + (((uint32_t)(32 * s + aHs)) ^ rx));
            #pragma unroll
            for (int jp = 0; jp < 8; jp++) {
                uint32_t b[4];
                int n = nbase + jp * 16 + bNoff;
                ldm_x4(b, B1u + (uint32_t)n * 256 + (((uint32_t)(32 * s + bHs)) ^ rx));
                mma16816h(acc[2 * jp],     a[0], a[1], a[2], a[3], b[0], b[1]);
                mma16816h(acc[2 * jp + 1], a[0], a[1], a[2], a[3], b[2], b[3]);
            }
        }

        // ---- per-role nonlinearity ----
        if (isH) {
            float s1 = 0.f, q1 = 0.f, s2 = 0.f, q2 = 0.f;
            #pragma unroll
            for (int j = 0; j < 16; j++) {
                s1 += acc[j][0] + acc[j][1];
                q1 += acc[j][0] * acc[j][0] + acc[j][1] * acc[j][1];
                s2 += acc[j][2] + acc[j][3];
                q2 += acc[j][2] * acc[j][2] + acc[j][3] * acc[j][3];
            }
            #pragma unroll
            for (int o = 1; o <= 2; o <<= 1) {
                s1 += __shfl_xor_sync(0xFFFFFFFFu, s1, o);
                q1 += __shfl_xor_sync(0xFFFFFFFFu, q1, o);
                s2 += __shfl_xor_sync(0xFFFFFFFFu, s2, o);
                q2 += __shfl_xor_sync(0xFFFFFFFFu, q2, o);
            }
            float mu1 = s1 * (1.f / 128.f), rs1 = rsqrtf(q1 * (1.f / 128.f) - mu1 * mu1 + EPSC);
            float mu2 = s2 * (1.f / 128.f), rs2 = rsqrtf(q2 * (1.f / 128.f) - mu2 * mu2 + EPSC);
            #pragma unroll
            for (int j = 0; j < 16; j++) {
                int col = j * 8 + 2 * t;
                float2 gv = *(const float2*)(g1 + col);
                float2 bv = *(const float2*)(be1 + col);
                acc[j][0] = fast_gelu((acc[j][0] - mu1) * rs1 * gv.x + bv.x);
                acc[j][1] = fast_gelu((acc[j][1] - mu1) * rs1 * gv.y + bv.y);
                acc[j][2] = fast_gelu((acc[j][2] - mu2) * rs2 * gv.x + bv.x);
                acc[j][3] = fast_gelu((acc[j][3] - mu2) * rs2 * gv.y + bv.y);
            }
            #pragma unroll
            for (int j = 0; j < 16; j++) {    // write A2 = gelu(h)
                __half2 p0 = __floats2half2_rn(acc[j][0], acc[j][1]);
                __half2 p1 = __floats2half2_rn(acc[j][2], acc[j][3]);
                int b = 16 * j + 4 * t;
                *(uint32_t*)(A2 + swb(lr, b))     = *(uint32_t*)&p0;
                *(uint32_t*)(A2 + swb(lr + 8, b)) = *(uint32_t*)&p1;
            }
        } else {
            #pragma unroll
            for (int j = 0; j < 16; j++)
                #pragma unroll
                for (int c = 0; c < 4; c++)
                    acc[j][c] = fast_sigmoid(acc[j][c]);
            #pragma unroll
            for (int j = 0; j < 8; j++) {
                int col = j * 8 + 2 * t;
                *(float2*)(G + gofs(lr, col))     = make_float2(acc[j][0], acc[j][1]);
                *(float2*)(G + gofs(lr + 8, col)) = make_float2(acc[j][2], acc[j][3]);
            }
        }
        PAIR_BAR(barid);   // A2 + G visible

        // ---- prefetch next tile's ea rows (streaming) ----
        int tnext = tile + gridDim.x;
        const int tld = (tnext < EDGE_TILES) ? tnext : tile;
        float4 ev[8];
        #pragma unroll
        for (int i = 0; i < 8; i++)
            ev[i] = __ldcs((const float4*)(ea + (size_t)(tld * 128 + stRow0 + i) * 128 + lane * 4));

        // ---- GEMM2 split: h -> n 0..63, gate -> n 64..127 (A from A2) ----
        const int nb2 = isH ? 0 : 64;
        float acc2[8][4];
        #pragma unroll
        for (int jl = 0; jl < 8; jl++)
            #pragma unroll
            for (int c = 0; c < 4; c++) acc2[jl][c] = 0.f;
        #pragma unroll
        for (int s = 0; s < 8; s++) {
            uint32_t a[4];
            ldm_x4(a, aBase2 + (((uint32_t)(32 * s + aHs)) ^ rx));
            #pragma unroll
            for (int jp = 0; jp < 4; jp++) {
                uint32_t b[4];
                int n = nb2 + jp * 16 + bNoff;
                ldm_x4(b, W2u + (uint32_t)n * 256 + (((uint32_t)(32 * s + bHs)) ^ rx));
                mma16816h(acc2[2 * jp],     a[0], a[1], a[2], a[3], b[0], b[1]);
                mma16816h(acc2[2 * jp + 1], a[0], a[1], a[2], a[3], b[2], b[3]);
            }
        }

        // ---- epilogue half per warp: r = (h2+b2)*gate + ea(fp16 from A1) ----
        float r[8][4];
        #pragma unroll
        for (int jl = 0; jl < 8; jl++) {
            int col = nb2 + jl * 8 + 2 * t;
            float2 bv = *(const float2*)(b2 + col);
            uint32_t ha = *(const uint32_t*)(A1 + swb(lr, 2 * col));
            uint32_t hb = *(const uint32_t*)(A1 + swb(lr + 8, 2 * col));
            float2 eA = __half22float2(*reinterpret_cast<const __half2*>(&ha));
            float2 eB = __half22float2(*reinterpret_cast<const __half2*>(&hb));
            float g0, g1v, g2, g3;
            if (isH) {
                float2 gA = *(const float2*)(G + gofs(lr, col));
                float2 gB = *(const float2*)(G + gofs(lr + 8, col));
                g0 = gA.x; g1v = gA.y; g2 = gB.x; g3 = gB.y;
            } else {
                g0 = acc[8 + jl][0]; g1v = acc[8 + jl][1];
                g2 = acc[8 + jl][2]; g3 = acc[8 + jl][3];
            }
            r[jl][0] = (acc2[jl][0] + bv.x) * g0 + eA.x;
            r[jl][1] = (acc2[jl][1] + bv.y) * g1v + eA.y;
            r[jl][2] = (acc2[jl][2] + bv.x) * g2 + eB.x;
            r[jl][3] = (acc2[jl][3] + bv.y) * g3 + eB.y;
        }

        // ---- final LN: partial sums + pair exchange ----
        float s1 = 0.f, q1 = 0.f, s2 = 0.f, q2 = 0.f;
        #pragma unroll
        for (int jl = 0; jl < 8; jl++) {
            s1 += r[jl][0] + r[jl][1];
            q1 += r[jl][0] * r[jl][0] + r[jl][1] * r[jl][1];
            s2 += r[jl][2] + r[jl][3];
            q2 += r[jl][2] * r[jl][2] + r[jl][3] * r[jl][3];
        }
        #pragma unroll
        for (int o = 1; o <= 2; o <<= 1) {
            s1 += __shfl_xor_sync(0xFFFFFFFFu, s1, o);
            q1 += __shfl_xor_sync(0xFFFFFFFFu, q1, o);
            s2 += __shfl_xor_sync(0xFFFFFFFFu, s2, o);
            q2 += __shfl_xor_sync(0xFFFFFFFFu, q2, o);
        }
        {
            float* sp = S + pw * 64 + (isH ? 0 : 32) + g * 4;
            if (t == 0) { sp[0] = s1; sp[1] = q1; sp[2] = s2; sp[3] = q2; }
        }
        PAIR_BAR(barid);   // S visible; all A1/G reads complete -> A1 writable
        {
            const float* sp = S + pw * 64 + (isH ? 32 : 0) + g * 4;
            s1 += sp[0]; q1 += sp[1]; s2 += sp[2]; q2 += sp[3];
        }
        float mu1 = s1 * (1.f / 128.f), rs1 = rsqrtf(q1 * (1.f / 128.f) - mu1 * mu1 + EPSC);
        float mu2 = s2 * (1.f / 128.f), rs2 = rsqrtf(q2 * (1.f / 128.f) - mu2 * mu2 + EPSC);

        // ---- stage next tile's A1 from prefetched registers ----
        #pragma unroll
        for (int i = 0; i < 8; i++) {
            __half2 h0 = __floats2half2_rn(ev[i].x, ev[i].y);
            __half2 h1 = __floats2half2_rn(ev[i].z, ev[i].w);
            *(uint2*)(A1 + swb(stRow0 + i, 8 * lane)) =
                make_uint2(*(uint32_t*)&h0, *(uint32_t*)&h1);
        }

        // ---- finish LN + streaming out stores ----
        #pragma unroll
        for (int jl = 0; jl < 8; jl++) {
            int col = nb2 + jl * 8 + 2 * t;
            float2 gv = *(const float2*)(gn + col);
            float2 bv = *(const float2*)(bn + col);
            float2 o1, o2;
            o1.x = (r[jl][0] - mu1) * rs1 * gv.x + bv.x;
            o1.y = (r[jl][1] - mu1) * rs1 * gv.y + bv.y;
            o2.x = (r[jl][2] - mu2) * rs2 * gv.x + bv.x;
            o2.y = (r[jl][3] - mu2) * rs2 * gv.y + bv.y;
            __stcs((float2*)(out + (size_t)e1 * 128 + col), o1);
            __stcs((float2*)(out + (size_t)e2 * 128 + col), o2);
        }
    }
}

// ---------------------------------------------------------------------------
extern "C" void kernel_launch(void* const* d_in, const int* in_sizes, int n_in,
                              void* d_out, int out_size)
{
    const float* x   = (const float*)d_in[0];
    const int*   ei  = (const int*)d_in[1];
    const float* ea  = (const float*)d_in[2];
    const float* W1  = (const float*)d_in[3];
    const float* b1  = (const float*)d_in[4];
    const float* g1  = (const float*)d_in[5];
    const float* be1 = (const float*)d_in[6];
    const float* W2  = (const float*)d_in[7];
    const float* b2  = (const float*)d_in[8];
    const float* Wg  = (const float*)d_in[9];
    const float* bg  = (const float*)d_in[10];
    const float* gn  = (const float*)d_in[11];
    const float* bn  = (const float*)d_in[12];
    float*       out = (float*)d_out;

    const int node_smem = 131072;
    const int edge_smem = 198656;
    cudaFuncSetAttribute(node_mma_kernel, cudaFuncAttributeMaxDynamicSharedMemorySize, node_smem);
    cudaFuncSetAttribute(edge_mma_kernel, cudaFuncAttributeMaxDynamicSharedMemorySize, edge_smem);

    prep_kernel<<<448, 256>>>(W1, Wg, W2);
    node_mma_kernel<<<GRID_P, 512, node_smem>>>(x);
    edge_mma_kernel<<<GRID_P, 512, edge_smem>>>(ei, ea, b1, g1, be1, b2, bg, gn, bn, out);
}